// round 1
// baseline (speedup 1.0000x reference)
#include <cuda_runtime.h>
#include <math.h>

#define CB   2
#define CT   2048
#define CDIM 1024
#define CH   16
#define CDH  64
#define MROWS (CB*CT)   // 4096

// scratch (allocation-free rule: device globals)
__device__ float g_q[MROWS*CDIM];
__device__ float g_k[MROWS*CDIM];
__device__ float g_v[MROWS*CDIM];
__device__ float g_att[MROWS*CDIM];

// ---------------------------------------------------------------------------
// C[M,N] = A[M,K] @ B[N,K]^T   (row-major, all dims multiples of tile sizes)
// 128x128 block tile, BK=16, 256 threads, 8x8 micro-tile (split 4+4).
// ---------------------------------------------------------------------------
__global__ __launch_bounds__(256) void gemm_nt_kernel(
    const float* __restrict__ A, const float* __restrict__ Bw,
    float* __restrict__ C, int M, int N, int K)
{
    __shared__ float As[16][128];
    __shared__ float Bs[16][128];
    const int tid = threadIdx.x;
    const int bm = blockIdx.y * 128;
    const int bn = blockIdx.x * 128;
    const int ty = tid >> 4;          // 0..15
    const int tx = tid & 15;          // 0..15

    const int ldRow = tid >> 1;       // 0..127
    const int ldK   = (tid & 1) * 8;  // 0 or 8

    const float* Ap = A  + (size_t)(bm + ldRow) * K + ldK;
    const float* Bp = Bw + (size_t)(bn + ldRow) * K + ldK;

    float acc[8][8];
#pragma unroll
    for (int i = 0; i < 8; i++)
#pragma unroll
        for (int j = 0; j < 8; j++) acc[i][j] = 0.f;

    for (int k0 = 0; k0 < K; k0 += 16) {
        float4 a0 = *(const float4*)(Ap + k0);
        float4 a1 = *(const float4*)(Ap + k0 + 4);
        float4 b0 = *(const float4*)(Bp + k0);
        float4 b1 = *(const float4*)(Bp + k0 + 4);
        As[ldK+0][ldRow]=a0.x; As[ldK+1][ldRow]=a0.y; As[ldK+2][ldRow]=a0.z; As[ldK+3][ldRow]=a0.w;
        As[ldK+4][ldRow]=a1.x; As[ldK+5][ldRow]=a1.y; As[ldK+6][ldRow]=a1.z; As[ldK+7][ldRow]=a1.w;
        Bs[ldK+0][ldRow]=b0.x; Bs[ldK+1][ldRow]=b0.y; Bs[ldK+2][ldRow]=b0.z; Bs[ldK+3][ldRow]=b0.w;
        Bs[ldK+4][ldRow]=b1.x; Bs[ldK+5][ldRow]=b1.y; Bs[ldK+6][ldRow]=b1.z; Bs[ldK+7][ldRow]=b1.w;
        __syncthreads();
#pragma unroll
        for (int kk = 0; kk < 16; kk++) {
            float4 av0 = *(const float4*)&As[kk][ty*4];
            float4 av1 = *(const float4*)&As[kk][64 + ty*4];
            float4 bv0 = *(const float4*)&Bs[kk][tx*4];
            float4 bv1 = *(const float4*)&Bs[kk][64 + tx*4];
            float ar[8] = {av0.x,av0.y,av0.z,av0.w, av1.x,av1.y,av1.z,av1.w};
            float br[8] = {bv0.x,bv0.y,bv0.z,bv0.w, bv1.x,bv1.y,bv1.z,bv1.w};
#pragma unroll
            for (int i = 0; i < 8; i++)
#pragma unroll
                for (int j = 0; j < 8; j++)
                    acc[i][j] = fmaf(ar[i], br[j], acc[i][j]);
        }
        __syncthreads();
    }

#pragma unroll
    for (int i = 0; i < 8; i++) {
        int r = bm + ((i >> 2) * 64) + ty * 4 + (i & 3);
        float4 v0 = make_float4(acc[i][0], acc[i][1], acc[i][2], acc[i][3]);
        float4 v1 = make_float4(acc[i][4], acc[i][5], acc[i][6], acc[i][7]);
        *(float4*)(C + (size_t)r * N + bn + tx*4)      = v0;
        *(float4*)(C + (size_t)r * N + bn + 64 + tx*4) = v1;
    }
}

// ---------------------------------------------------------------------------
// RoPE in-place on q and k. One thread per (b,t,h,half) pair, half in [0,32).
// ---------------------------------------------------------------------------
__global__ void rope_kernel(float* __restrict__ q, float* __restrict__ k)
{
    int i = blockIdx.x * blockDim.x + threadIdx.x;
    if (i >= CB*CT*CH*32) return;
    int half = i & 31;
    int rest = i >> 5;                       // (b*CT + t)*CH + h
    int t = (rest / CH) & (CT - 1);
    // inv_freq = 10000^{-half/32}
    float inv = expf(-(float)half * (1.0f/32.0f) * logf(10000.0f));
    float ang = (float)t * inv;
    float sv, cv;
    sincosf(ang, &sv, &cv);
    size_t base = (size_t)rest * CDH;
    float x0 = q[base + half], x1 = q[base + half + 32];
    q[base + half]      = x0 * cv - x1 * sv;
    q[base + half + 32] = x1 * cv + x0 * sv;
    float y0 = k[base + half], y1 = k[base + half + 32];
    k[base + half]      = y0 * cv - y1 * sv;
    k[base + half + 32] = y1 * cv + y0 * sv;
}

// ---------------------------------------------------------------------------
// Causal flash attention. One block = (b, h, 64 q-rows). 256 threads (16x16).
// Qs/Ks stored d-major (transposed) for conflict-free float4 reads.
// Ps row-major with pad 65 for broadcast reads in PV.
// ---------------------------------------------------------------------------
#define ATTN_SMEM_BYTES ((3*64*64 + 64*65) * 4)   // 65792 B

__global__ __launch_bounds__(256) void attn_kernel(float* __restrict__ outp)
{
    extern __shared__ float sm[];
    float* Qs = sm;                  // [d][r], 64x64
    float* Ks = sm + 4096;           // [d][c], 64x64
    float* Vs = sm + 8192;           // [j][d], 64x64
    float* Ps = sm + 12288;          // [r][j], stride 65

    const int tid = threadIdx.x;
    const int q0 = blockIdx.x * 64;
    const int h  = blockIdx.y;
    const int b  = blockIdx.z;
    const int ty = tid >> 4, tx = tid & 15;
    const int r0 = ty * 4,  c0 = tx * 4;

    const float* qg = g_q + (size_t)b * CT * CDIM + (size_t)h * CDH;
    const float* kg = g_k + (size_t)b * CT * CDIM + (size_t)h * CDH;
    const float* vg = g_v + (size_t)b * CT * CDIM + (size_t)h * CDH;

    // Load Q tile transposed: Qs[d][r]
    {
        int r = tid & 63;
        int g = tid >> 6;
#pragma unroll
        for (int it = 0; it < 4; it++) {
            int d4 = (it * 4 + g) * 4;
            float4 v = *(const float4*)(qg + (size_t)(q0 + r) * CDIM + d4);
            Qs[(d4+0)*64 + r] = v.x;
            Qs[(d4+1)*64 + r] = v.y;
            Qs[(d4+2)*64 + r] = v.z;
            Qs[(d4+3)*64 + r] = v.w;
        }
    }

    float m_i[4], l_i[4], o[4][4];
#pragma unroll
    for (int i = 0; i < 4; i++) {
        m_i[i] = -1e30f; l_i[i] = 0.f;
#pragma unroll
        for (int j = 0; j < 4; j++) o[i][j] = 0.f;
    }

    for (int j0 = 0; j0 <= q0; j0 += 64) {
        __syncthreads();   // previous tile's smem reads done
        // K tile transposed
        {
            int r = tid & 63;
            int g = tid >> 6;
#pragma unroll
            for (int it = 0; it < 4; it++) {
                int d4 = (it * 4 + g) * 4;
                float4 v = *(const float4*)(kg + (size_t)(j0 + r) * CDIM + d4);
                Ks[(d4+0)*64 + r] = v.x;
                Ks[(d4+1)*64 + r] = v.y;
                Ks[(d4+2)*64 + r] = v.z;
                Ks[(d4+3)*64 + r] = v.w;
            }
        }
        // V tile natural
#pragma unroll
        for (int it = 0; it < 4; it++) {
            int task = it * 256 + tid;
            int j  = task >> 4;
            int d4 = (task & 15) * 4;
            *(float4*)&Vs[j*64 + d4] =
                *(const float4*)(vg + (size_t)(j0 + j) * CDIM + d4);
        }
        __syncthreads();

        // S = Q K^T (4x4 per thread)
        float s[4][4];
#pragma unroll
        for (int i = 0; i < 4; i++)
#pragma unroll
            for (int j = 0; j < 4; j++) s[i][j] = 0.f;
#pragma unroll 16
        for (int d = 0; d < 64; d++) {
            float4 qa = *(const float4*)&Qs[d*64 + r0];
            float4 kb = *(const float4*)&Ks[d*64 + c0];
            float ar[4] = {qa.x, qa.y, qa.z, qa.w};
            float br[4] = {kb.x, kb.y, kb.z, kb.w};
#pragma unroll
            for (int i = 0; i < 4; i++)
#pragma unroll
                for (int j = 0; j < 4; j++)
                    s[i][j] = fmaf(ar[i], br[j], s[i][j]);
        }
#pragma unroll
        for (int i = 0; i < 4; i++)
#pragma unroll
            for (int j = 0; j < 4; j++) s[i][j] *= 0.125f;  // Dh^-0.5
        if (j0 == q0) {
#pragma unroll
            for (int i = 0; i < 4; i++)
#pragma unroll
                for (int j = 0; j < 4; j++)
                    if (c0 + j > r0 + i) s[i][j] = -1e30f;
        }

        // online softmax (row groups of 16 lanes: xor 8,4,2,1 stays in group)
#pragma unroll
        for (int i = 0; i < 4; i++) {
            float mx = fmaxf(fmaxf(s[i][0], s[i][1]), fmaxf(s[i][2], s[i][3]));
#pragma unroll
            for (int off = 8; off; off >>= 1)
                mx = fmaxf(mx, __shfl_xor_sync(0xffffffffu, mx, off));
            float mnew  = fmaxf(m_i[i], mx);
            float alpha = __expf(m_i[i] - mnew);
            float rs = 0.f;
#pragma unroll
            for (int j = 0; j < 4; j++) {
                float p = __expf(s[i][j] - mnew);
                s[i][j] = p; rs += p;
            }
#pragma unroll
            for (int off = 8; off; off >>= 1)
                rs += __shfl_xor_sync(0xffffffffu, rs, off);
            l_i[i] = l_i[i] * alpha + rs;
            m_i[i] = mnew;
#pragma unroll
            for (int j = 0; j < 4; j++) o[i][j] *= alpha;
        }

        // stage P (row-major, pad 65)
#pragma unroll
        for (int i = 0; i < 4; i++)
#pragma unroll
            for (int j = 0; j < 4; j++)
                Ps[(r0+i)*65 + c0 + j] = s[i][j];
        __syncthreads();

        // O += P @ V
#pragma unroll 8
        for (int j = 0; j < 64; j++) {
            float4 vv = *(const float4*)&Vs[j*64 + c0];
            float vr[4] = {vv.x, vv.y, vv.z, vv.w};
#pragma unroll
            for (int i = 0; i < 4; i++) {
                float p = Ps[(r0+i)*65 + j];
#pragma unroll
                for (int jj = 0; jj < 4; jj++)
                    o[i][jj] = fmaf(p, vr[jj], o[i][jj]);
            }
        }
    }

    // write normalized output: (b, q0+r, h*64 + c0..c0+3)
#pragma unroll
    for (int i = 0; i < 4; i++) {
        float inv = 1.0f / l_i[i];
        float4 res = make_float4(o[i][0]*inv, o[i][1]*inv, o[i][2]*inv, o[i][3]*inv);
        *(float4*)(outp + ((size_t)b*CT + q0 + r0 + i) * CDIM + h*CDH + c0) = res;
    }
}

// ---------------------------------------------------------------------------
extern "C" void kernel_launch(void* const* d_in, const int* in_sizes, int n_in,
                              void* d_out, int out_size)
{
    const float* x  = (const float*)d_in[0];
    const float* Wq = (const float*)d_in[1];
    const float* Wk = (const float*)d_in[2];
    const float* Wv = (const float*)d_in[3];
    const float* Wo = (const float*)d_in[4];
    // d_in[5] = mask (tril) — causality implemented directly
    float* out = (float*)d_out;

    float *qp, *kp, *vp, *ap;
    cudaGetSymbolAddress((void**)&qp, g_q);
    cudaGetSymbolAddress((void**)&kp, g_k);
    cudaGetSymbolAddress((void**)&vp, g_v);
    cudaGetSymbolAddress((void**)&ap, g_att);

    dim3 gg(CDIM/128, MROWS/128);   // (8, 32)
    gemm_nt_kernel<<<gg, 256>>>(x, Wq, qp, MROWS, CDIM, CDIM);
    gemm_nt_kernel<<<gg, 256>>>(x, Wk, kp, MROWS, CDIM, CDIM);
    gemm_nt_kernel<<<gg, 256>>>(x, Wv, vp, MROWS, CDIM, CDIM);

    int nrope = CB*CT*CH*32;
    rope_kernel<<<(nrope + 255)/256, 256>>>(qp, kp);

    cudaFuncSetAttribute(attn_kernel, cudaFuncAttributeMaxDynamicSharedMemorySize,
                         ATTN_SMEM_BYTES);
    attn_kernel<<<dim3(CT/64, CH, CB), 256, ATTN_SMEM_BYTES>>>(ap);

    gemm_nt_kernel<<<gg, 256>>>(ap, Wo, out, MROWS, CDIM, CDIM);
}

// round 5
// speedup vs baseline: 1.5043x; 1.5043x over previous
#include <cuda_runtime.h>
#include <cuda_bf16.h>
#include <math.h>
#include <cstdint>

#define CB   2
#define CT   2048
#define CDIM 1024
#define CH   16
#define CDH  64
#define MROWS (CB*CT)       // 4096
#define KSPLIT (3*CDIM)     // 3072
#define NSTAGE (KSPLIT/64)  // 48

// ---------------- scratch (device globals; no allocation allowed) ----------
__device__ float g_q[MROWS*CDIM];
__device__ float g_k[MROWS*CDIM];
__device__ float g_v[MROWS*CDIM];
__device__ float g_att[MROWS*CDIM];
__device__ __nv_bfloat16 g_a [MROWS*KSPLIT];   // split activations [Ah|Ah|Al]
__device__ __nv_bfloat16 g_wq[CDIM*KSPLIT];    // split weights     [Bh|Bl|Bh]
__device__ __nv_bfloat16 g_wk[CDIM*KSPLIT];
__device__ __nv_bfloat16 g_wv[CDIM*KSPLIT];
__device__ __nv_bfloat16 g_wo[CDIM*KSPLIT];

__device__ __forceinline__ uint32_t smem_u32(const void* p) {
    uint32_t a;
    asm("{ .reg .u64 t; cvta.to.shared.u64 t, %1; cvt.u32.u64 %0, t; }"
        : "=r"(a) : "l"(p));
    return a;
}

// ---------------------------------------------------------------------------
// split conversion: in fp32 [rows x 1024] -> out bf16 [rows x 3072]
// mode 0 (activations): [h | h | l]    mode 1 (weights): [h | l | h]
// ---------------------------------------------------------------------------
__global__ void split_kernel(const float* __restrict__ in,
                             __nv_bfloat16* __restrict__ out,
                             int rows, int mode)
{
    int i = blockIdx.x * blockDim.x + threadIdx.x;
    if (i >= rows * 256) return;
    int r  = i >> 8;
    int c4 = (i & 255) * 4;
    float4 v = *(const float4*)(in + (size_t)r * CDIM + c4);
    __nv_bfloat16 h[4], l[4];
    float vs[4] = {v.x, v.y, v.z, v.w};
#pragma unroll
    for (int t = 0; t < 4; t++) {
        h[t] = __float2bfloat16(vs[t]);
        l[t] = __float2bfloat16(vs[t] - __bfloat162float(h[t]));
    }
    __nv_bfloat16* o = out + (size_t)r * KSPLIT + c4;
    *(ushort4*)(o)                 = *(ushort4*)h;
    *(ushort4*)(o + CDIM)          = mode ? *(ushort4*)l : *(ushort4*)h;
    *(ushort4*)(o + 2 * CDIM)      = mode ? *(ushort4*)h : *(ushort4*)l;
}

// ---------------------------------------------------------------------------
// mma.sync bf16 NT GEMM: C[M,N] = A'[M,3072] * B'[N,3072]^T, fp32 accum.
// CTA 128x128, BK=64 (128B rows, SW128 swizzle), 8 warps (2x4, 64x32 each),
// cp.async double buffering, ldmatrix operand loads.
// ---------------------------------------------------------------------------
#define GEMM_SMEM (4*16384)   // 2 stages x (A 16KB + B 16KB)

__global__ __launch_bounds__(256)
void gemm_mma_kernel(const __nv_bfloat16* __restrict__ A,
                     const __nv_bfloat16* __restrict__ B,
                     float* __restrict__ C, int M, int N)
{
    extern __shared__ char sm[];
    const uint32_t smb = smem_u32(sm);

    const int tid  = threadIdx.x;
    const int lane = tid & 31;
    const int wid  = tid >> 5;
    const int warp_m = wid & 1;     // 0..1 -> 64 rows
    const int warp_n = wid >> 1;    // 0..3 -> 32 cols
    const int bm = blockIdx.y * 128;
    const int bn = blockIdx.x * 128;

    const __nv_bfloat16* Ag = A + (size_t)bm * KSPLIT;
    const __nv_bfloat16* Bg = B + (size_t)bn * KSPLIT;

    // cp.async mapping: 1024 16B-chunks per tile, 4 per thread
    const int crow = tid >> 3;          // 0..31
    const int cch  = tid & 7;           // chunk in 128B row
    uint32_t dsto[4];
#pragma unroll
    for (int i = 0; i < 4; i++) {
        int r = crow + 32 * i;
        uint32_t o = r * 128 + cch * 16;
        o ^= (o >> 3) & 0x70;           // SW128 swizzle
        dsto[i] = o;
    }

    auto prefetch = [&](int s) {
        const int buf = s & 1;
        const uint32_t abase = smb + buf * 32768;
        const uint32_t bbase = abase + 16384;
        const __nv_bfloat16* a = Ag + s * 64;
        const __nv_bfloat16* b = Bg + s * 64;
#pragma unroll
        for (int i = 0; i < 4; i++) {
            int r = crow + 32 * i;
            const void* pa = a + (size_t)r * KSPLIT + cch * 8;
            const void* pb = b + (size_t)r * KSPLIT + cch * 8;
            asm volatile("cp.async.cg.shared.global [%0], [%1], 16;"
                         :: "r"(abase + dsto[i]), "l"(pa));
            asm volatile("cp.async.cg.shared.global [%0], [%1], 16;"
                         :: "r"(bbase + dsto[i]), "l"(pb));
        }
        asm volatile("cp.async.commit_group;");
    };

    float acc[4][4][4];
#pragma unroll
    for (int mt = 0; mt < 4; mt++)
#pragma unroll
        for (int nt = 0; nt < 4; nt++)
#pragma unroll
            for (int e = 0; e < 4; e++) acc[mt][nt][e] = 0.f;

    prefetch(0);

    for (int s = 0; s < NSTAGE; s++) {
        if (s + 1 < NSTAGE) {
            prefetch(s + 1);
            asm volatile("cp.async.wait_group 1;");
        } else {
            asm volatile("cp.async.wait_group 0;");
        }
        __syncthreads();

        const int buf = s & 1;
        const uint32_t abase = smb + buf * 32768;
        const uint32_t bbase = abase + 16384;

#pragma unroll
        for (int kk = 0; kk < 4; kk++) {
            // A fragments: 4 x m16 tiles
            uint32_t af[4][4];
            {
                const int ar = warp_m * 64 + (lane & 15);
                const int ac = kk * 2 + (lane >> 4);
#pragma unroll
                for (int mt = 0; mt < 4; mt++) {
                    uint32_t o = (ar + mt * 16) * 128 + ac * 16;
                    o ^= (o >> 3) & 0x70;
                    asm volatile(
                        "ldmatrix.sync.aligned.m8n8.x4.shared.b16 {%0,%1,%2,%3}, [%4];"
                        : "=r"(af[mt][0]), "=r"(af[mt][1]),
                          "=r"(af[mt][2]), "=r"(af[mt][3])
                        : "r"(abase + o));
                }
            }
            // B fragments: 4 x n8 tiles
            uint32_t bf[4][2];
            {
                const int br = warp_n * 32 + (lane & 7);
                const int bc = kk * 2 + ((lane >> 3) & 1);
#pragma unroll
                for (int nt = 0; nt < 4; nt++) {
                    uint32_t o = (br + nt * 8) * 128 + bc * 16;
                    o ^= (o >> 3) & 0x70;
                    asm volatile(
                        "ldmatrix.sync.aligned.m8n8.x2.shared.b16 {%0,%1}, [%2];"
                        : "=r"(bf[nt][0]), "=r"(bf[nt][1])
                        : "r"(bbase + o));
                }
            }
#pragma unroll
            for (int mt = 0; mt < 4; mt++)
#pragma unroll
                for (int nt = 0; nt < 4; nt++) {
                    asm volatile(
                        "mma.sync.aligned.m16n8k16.row.col.f32.bf16.bf16.f32 "
                        "{%0,%1,%2,%3}, {%4,%5,%6,%7}, {%8,%9}, {%0,%1,%2,%3};"
                        : "+f"(acc[mt][nt][0]), "+f"(acc[mt][nt][1]),
                          "+f"(acc[mt][nt][2]), "+f"(acc[mt][nt][3])
                        : "r"(af[mt][0]), "r"(af[mt][1]),
                          "r"(af[mt][2]), "r"(af[mt][3]),
                          "r"(bf[nt][0]), "r"(bf[nt][1]));
                }
        }
        __syncthreads();   // before next prefetch overwrites the other buffer
    }

    // epilogue: thread t owns rows (t/4, t/4+8), cols 2*(t%4)+{0,1} per tile
    const int er = lane >> 2;
    const int ec = (lane & 3) * 2;
#pragma unroll
    for (int mt = 0; mt < 4; mt++) {
        int r0 = bm + warp_m * 64 + mt * 16 + er;
#pragma unroll
        for (int nt = 0; nt < 4; nt++) {
            int cc = bn + warp_n * 32 + nt * 8 + ec;
            *(float2*)(C + (size_t)r0 * N + cc) =
                make_float2(acc[mt][nt][0], acc[mt][nt][1]);
            *(float2*)(C + (size_t)(r0 + 8) * N + cc) =
                make_float2(acc[mt][nt][2], acc[mt][nt][3]);
        }
    }
}

// ---------------------------------------------------------------------------
// RoPE in-place on q and k.
// ---------------------------------------------------------------------------
__global__ void rope_kernel(float* __restrict__ q, float* __restrict__ k)
{
    int i = blockIdx.x * blockDim.x + threadIdx.x;
    if (i >= CB*CT*CH*32) return;
    int half = i & 31;
    int rest = i >> 5;
    int t = (rest / CH) & (CT - 1);
    float inv = expf(-(float)half * (1.0f/32.0f) * logf(10000.0f));
    float ang = (float)t * inv;
    float sv, cv;
    sincosf(ang, &sv, &cv);
    size_t base = (size_t)rest * CDH;
    float x0 = q[base + half], x1 = q[base + half + 32];
    q[base + half]      = x0 * cv - x1 * sv;
    q[base + half + 32] = x1 * cv + x0 * sv;
    float y0 = k[base + half], y1 = k[base + half + 32];
    k[base + half]      = y0 * cv - y1 * sv;
    k[base + half + 32] = y1 * cv + y0 * sv;
}

// ---------------------------------------------------------------------------
// Causal flash attention (fp32 SIMT).
// ---------------------------------------------------------------------------
#define ATTN_SMEM_BYTES ((3*64*64 + 64*65) * 4)

__global__ __launch_bounds__(256) void attn_kernel(float* __restrict__ outp)
{
    extern __shared__ float smf[];
    float* Qs = smf;
    float* Ks = smf + 4096;
    float* Vs = smf + 8192;
    float* Ps = smf + 12288;

    const int tid = threadIdx.x;
    const int q0 = blockIdx.x * 64;
    const int h  = blockIdx.y;
    const int b  = blockIdx.z;
    const int ty = tid >> 4, tx = tid & 15;
    const int r0 = ty * 4,  c0 = tx * 4;

    const float* qg = g_q + (size_t)b * CT * CDIM + (size_t)h * CDH;
    const float* kg = g_k + (size_t)b * CT * CDIM + (size_t)h * CDH;
    const float* vg = g_v + (size_t)b * CT * CDIM + (size_t)h * CDH;

    {
        int r = tid & 63;
        int g = tid >> 6;
#pragma unroll
        for (int it = 0; it < 4; it++) {
            int d4 = (it * 4 + g) * 4;
            float4 v = *(const float4*)(qg + (size_t)(q0 + r) * CDIM + d4);
            Qs[(d4+0)*64 + r] = v.x;
            Qs[(d4+1)*64 + r] = v.y;
            Qs[(d4+2)*64 + r] = v.z;
            Qs[(d4+3)*64 + r] = v.w;
        }
    }

    float m_i[4], l_i[4], o[4][4];
#pragma unroll
    for (int i = 0; i < 4; i++) {
        m_i[i] = -1e30f; l_i[i] = 0.f;
#pragma unroll
        for (int j = 0; j < 4; j++) o[i][j] = 0.f;
    }

    for (int j0 = 0; j0 <= q0; j0 += 64) {
        __syncthreads();
        {
            int r = tid & 63;
            int g = tid >> 6;
#pragma unroll
            for (int it = 0; it < 4; it++) {
                int d4 = (it * 4 + g) * 4;
                float4 v = *(const float4*)(kg + (size_t)(j0 + r) * CDIM + d4);
                Ks[(d4+0)*64 + r] = v.x;
                Ks[(d4+1)*64 + r] = v.y;
                Ks[(d4+2)*64 + r] = v.z;
                Ks[(d4+3)*64 + r] = v.w;
            }
        }
#pragma unroll
        for (int it = 0; it < 4; it++) {
            int task = it * 256 + tid;
            int j  = task >> 4;
            int d4 = (task & 15) * 4;
            *(float4*)&Vs[j*64 + d4] =
                *(const float4*)(vg + (size_t)(j0 + j) * CDIM + d4);
        }
        __syncthreads();

        float s[4][4];
#pragma unroll
        for (int i = 0; i < 4; i++)
#pragma unroll
            for (int j = 0; j < 4; j++) s[i][j] = 0.f;
#pragma unroll 16
        for (int d = 0; d < 64; d++) {
            float4 qa = *(const float4*)&Qs[d*64 + r0];
            float4 kb = *(const float4*)&Ks[d*64 + c0];
            float ar[4] = {qa.x, qa.y, qa.z, qa.w};
            float br[4] = {kb.x, kb.y, kb.z, kb.w};
#pragma unroll
            for (int i = 0; i < 4; i++)
#pragma unroll
                for (int j = 0; j < 4; j++)
                    s[i][j] = fmaf(ar[i], br[j], s[i][j]);
        }
#pragma unroll
        for (int i = 0; i < 4; i++)
#pragma unroll
            for (int j = 0; j < 4; j++) s[i][j] *= 0.125f;
        if (j0 == q0) {
#pragma unroll
            for (int i = 0; i < 4; i++)
#pragma unroll
                for (int j = 0; j < 4; j++)
                    if (c0 + j > r0 + i) s[i][j] = -1e30f;
        }

#pragma unroll
        for (int i = 0; i < 4; i++) {
            float mx = fmaxf(fmaxf(s[i][0], s[i][1]), fmaxf(s[i][2], s[i][3]));
#pragma unroll
            for (int off = 8; off; off >>= 1)
                mx = fmaxf(mx, __shfl_xor_sync(0xffffffffu, mx, off));
            float mnew  = fmaxf(m_i[i], mx);
            float alpha = __expf(m_i[i] - mnew);
            float rs = 0.f;
#pragma unroll
            for (int j = 0; j < 4; j++) {
                float p = __expf(s[i][j] - mnew);
                s[i][j] = p; rs += p;
            }
#pragma unroll
            for (int off = 8; off; off >>= 1)
                rs += __shfl_xor_sync(0xffffffffu, rs, off);
            l_i[i] = l_i[i] * alpha + rs;
            m_i[i] = mnew;
#pragma unroll
            for (int j = 0; j < 4; j++) o[i][j] *= alpha;
        }

#pragma unroll
        for (int i = 0; i < 4; i++)
#pragma unroll
            for (int j = 0; j < 4; j++)
                Ps[(r0+i)*65 + c0 + j] = s[i][j];
        __syncthreads();

#pragma unroll 8
        for (int j = 0; j < 64; j++) {
            float4 vv = *(const float4*)&Vs[j*64 + c0];
            float vr[4] = {vv.x, vv.y, vv.z, vv.w};
#pragma unroll
            for (int i = 0; i < 4; i++) {
                float p = Ps[(r0+i)*65 + j];
#pragma unroll
                for (int jj = 0; jj < 4; jj++)
                    o[i][jj] = fmaf(p, vr[jj], o[i][jj]);
            }
        }
    }

#pragma unroll
    for (int i = 0; i < 4; i++) {
        float inv = 1.0f / l_i[i];
        float4 res = make_float4(o[i][0]*inv, o[i][1]*inv, o[i][2]*inv, o[i][3]*inv);
        *(float4*)(outp + ((size_t)b*CT + q0 + r0 + i) * CDIM + h*CDH + c0) = res;
    }
}

// ---------------------------------------------------------------------------
extern "C" void kernel_launch(void* const* d_in, const int* in_sizes, int n_in,
                              void* d_out, int out_size)
{
    const float* x  = (const float*)d_in[0];
    const float* Wq = (const float*)d_in[1];
    const float* Wk = (const float*)d_in[2];
    const float* Wv = (const float*)d_in[3];
    const float* Wo = (const float*)d_in[4];
    float* out = (float*)d_out;

    float *qp, *kp, *vp, *ap;
    __nv_bfloat16 *a2, *wq2, *wk2, *wv2, *wo2;
    cudaGetSymbolAddress((void**)&qp, g_q);
    cudaGetSymbolAddress((void**)&kp, g_k);
    cudaGetSymbolAddress((void**)&vp, g_v);
    cudaGetSymbolAddress((void**)&ap, g_att);
    cudaGetSymbolAddress((void**)&a2, g_a);
    cudaGetSymbolAddress((void**)&wq2, g_wq);
    cudaGetSymbolAddress((void**)&wk2, g_wk);
    cudaGetSymbolAddress((void**)&wv2, g_wv);
    cudaGetSymbolAddress((void**)&wo2, g_wo);

    cudaFuncSetAttribute(gemm_mma_kernel,
                         cudaFuncAttributeMaxDynamicSharedMemorySize, GEMM_SMEM);
    cudaFuncSetAttribute(attn_kernel,
                         cudaFuncAttributeMaxDynamicSharedMemorySize, ATTN_SMEM_BYTES);

    // split conversions
    int na = MROWS * 256, nw = CDIM * 256;
    split_kernel<<<(na + 255)/256, 256>>>(x,  a2,  MROWS, 0);
    split_kernel<<<(nw + 255)/256, 256>>>(Wq, wq2, CDIM, 1);
    split_kernel<<<(nw + 255)/256, 256>>>(Wk, wk2, CDIM, 1);
    split_kernel<<<(nw + 255)/256, 256>>>(Wv, wv2, CDIM, 1);
    split_kernel<<<(nw + 255)/256, 256>>>(Wo, wo2, CDIM, 1);

    dim3 gg(CDIM/128, MROWS/128);   // (8, 32)
    gemm_mma_kernel<<<gg, 256, GEMM_SMEM>>>(a2, wq2, qp, MROWS, CDIM);
    gemm_mma_kernel<<<gg, 256, GEMM_SMEM>>>(a2, wk2, kp, MROWS, CDIM);
    gemm_mma_kernel<<<gg, 256, GEMM_SMEM>>>(a2, wv2, vp, MROWS, CDIM);

    int nrope = CB*CT*CH*32;
    rope_kernel<<<(nrope + 255)/256, 256>>>(qp, kp);

    attn_kernel<<<dim3(CT/64, CH, CB), 256, ATTN_SMEM_BYTES>>>(ap);

    split_kernel<<<(na + 255)/256, 256>>>(ap, a2, MROWS, 0);
    gemm_mma_kernel<<<gg, 256, GEMM_SMEM>>>(a2, wo2, out, MROWS, CDIM);
}

// round 6
// speedup vs baseline: 2.8095x; 1.8676x over previous
#include <cuda_runtime.h>
#include <cuda_bf16.h>
#include <math.h>
#include <cstdint>

#define CB   2
#define CT   2048
#define CDIM 1024
#define CH   16
#define CDH  64
#define MROWS (CB*CT)       // 4096
#define KSPLIT (3*CDIM)     // 3072
#define NSTAGE (KSPLIT/64)  // 48

// ---------------- scratch (device globals) ----------------------------------
__device__ float g_q[MROWS*CDIM];
__device__ float g_k[MROWS*CDIM];
__device__ float g_v[MROWS*CDIM];
__device__ float g_att[MROWS*CDIM];
__device__ __nv_bfloat16 g_a [MROWS*KSPLIT];   // split activations [Ah|Ah|Al]
__device__ __nv_bfloat16 g_wq[CDIM*KSPLIT];    // split weights     [Bh|Bl|Bh]
__device__ __nv_bfloat16 g_wk[CDIM*KSPLIT];
__device__ __nv_bfloat16 g_wv[CDIM*KSPLIT];
__device__ __nv_bfloat16 g_wo[CDIM*KSPLIT];
// pre-split attention operands (same linear layout as g_q/g_k/g_v)
__device__ __nv_bfloat16 g_qh[MROWS*CDIM];
__device__ __nv_bfloat16 g_ql[MROWS*CDIM];
__device__ __nv_bfloat16 g_kh[MROWS*CDIM];
__device__ __nv_bfloat16 g_kl[MROWS*CDIM];
__device__ __nv_bfloat16 g_vh[MROWS*CDIM];
__device__ __nv_bfloat16 g_vl[MROWS*CDIM];

__device__ __forceinline__ uint32_t smem_u32(const void* p) {
    uint32_t a;
    asm("{ .reg .u64 t; cvta.to.shared.u64 t, %1; cvt.u32.u64 %0, t; }"
        : "=r"(a) : "l"(p));
    return a;
}
__device__ __forceinline__ void ldsm4(uint32_t* r, uint32_t addr) {
    asm volatile("ldmatrix.sync.aligned.m8n8.x4.shared.b16 {%0,%1,%2,%3}, [%4];"
        : "=r"(r[0]), "=r"(r[1]), "=r"(r[2]), "=r"(r[3]) : "r"(addr));
}
__device__ __forceinline__ void ldsm2t(uint32_t* r, uint32_t addr) {
    asm volatile("ldmatrix.sync.aligned.m8n8.x2.trans.shared.b16 {%0,%1}, [%2];"
        : "=r"(r[0]), "=r"(r[1]) : "r"(addr));
}
__device__ __forceinline__ void mma16816(float* d, const uint32_t* a, const uint32_t* b) {
    asm volatile("mma.sync.aligned.m16n8k16.row.col.f32.bf16.bf16.f32 "
        "{%0,%1,%2,%3}, {%4,%5,%6,%7}, {%8,%9}, {%0,%1,%2,%3};"
        : "+f"(d[0]), "+f"(d[1]), "+f"(d[2]), "+f"(d[3])
        : "r"(a[0]), "r"(a[1]), "r"(a[2]), "r"(a[3]), "r"(b[0]), "r"(b[1]));
}
__device__ __forceinline__ float ex2f(float x) {
    float y; asm("ex2.approx.f32 %0, %1;" : "=f"(y) : "f"(x)); return y;
}
__device__ __forceinline__ uint32_t packbf(float a, float b) {
    __nv_bfloat162 t = __floats2bfloat162_rn(a, b);
    return *(uint32_t*)&t;
}
#define CPA16(dst, src) \
    asm volatile("cp.async.cg.shared.global [%0], [%1], 16;" :: "r"(dst), "l"(src))

// ---------------------------------------------------------------------------
// split: fp32 [rows x 1024] -> bf16 [rows x 3072]
// mode 0 (activations): [h|h|l]   mode 1 (weights): [h|l|h]
// ---------------------------------------------------------------------------
__global__ void split_kernel(const float* __restrict__ in,
                             __nv_bfloat16* __restrict__ out,
                             int rows, int mode)
{
    int i = blockIdx.x * blockDim.x + threadIdx.x;
    if (i >= rows * 256) return;
    int r  = i >> 8;
    int c4 = (i & 255) * 4;
    float4 v = *(const float4*)(in + (size_t)r * CDIM + c4);
    __nv_bfloat16 h[4], l[4];
    float vs[4] = {v.x, v.y, v.z, v.w};
#pragma unroll
    for (int t = 0; t < 4; t++) {
        h[t] = __float2bfloat16(vs[t]);
        l[t] = __float2bfloat16(vs[t] - __bfloat162float(h[t]));
    }
    __nv_bfloat16* o = out + (size_t)r * KSPLIT + c4;
    *(ushort4*)(o)            = *(ushort4*)h;
    *(ushort4*)(o + CDIM)     = mode ? *(ushort4*)l : *(ushort4*)h;
    *(ushort4*)(o + 2 * CDIM) = mode ? *(ushort4*)h : *(ushort4*)l;
}

// ---------------------------------------------------------------------------
// mma.sync bf16 NT GEMM: C = A'[M,3072] * B'[N,3072]^T, fp32 accum.
// CTA 128x256, 8 warps 2x4 with 64x64 warp tiles, 3-stage cp.async.
// ---------------------------------------------------------------------------
#define GEMM_SMEM (3*49152)

__global__ __launch_bounds__(256, 1)
void gemm_mma_kernel(const __nv_bfloat16* __restrict__ A,
                     const __nv_bfloat16* __restrict__ B,
                     float* __restrict__ C, int M, int N)
{
    extern __shared__ char sm[];
    const uint32_t smb = smem_u32(sm);
    const int tid  = threadIdx.x;
    const int lane = tid & 31;
    const int wid  = tid >> 5;
    const int wm = wid & 1;    // 0..1 -> 64 rows
    const int wn = wid >> 1;   // 0..3 -> 64 cols
    const int bm = blockIdx.y * 128;
    const int bn = blockIdx.x * 256;

    const __nv_bfloat16* Ag = A + (size_t)bm * KSPLIT;
    const __nv_bfloat16* Bg = B + (size_t)bn * KSPLIT;

    auto prefetch = [&](int s) {
        const int buf = s % 3;
        const uint32_t ab = smb + buf * 49152;
        const uint32_t bb = ab + 16384;
        const __nv_bfloat16* a = Ag + s * 64;
        const __nv_bfloat16* b = Bg + s * 64;
#pragma unroll
        for (int i = 0; i < 4; i++) {
            int idx = tid + i * 256;
            int r = idx >> 3, ch = idx & 7;
            uint32_t o = r * 128 + ch * 16; o ^= (o >> 3) & 0x70;
            CPA16(ab + o, a + (size_t)r * KSPLIT + ch * 8);
        }
#pragma unroll
        for (int i = 0; i < 8; i++) {
            int idx = tid + i * 256;
            int r = idx >> 3, ch = idx & 7;
            uint32_t o = r * 128 + ch * 16; o ^= (o >> 3) & 0x70;
            CPA16(bb + o, b + (size_t)r * KSPLIT + ch * 8);
        }
        asm volatile("cp.async.commit_group;");
    };

    float acc[4][8][4];
#pragma unroll
    for (int mt = 0; mt < 4; mt++)
#pragma unroll
        for (int nt = 0; nt < 8; nt++)
#pragma unroll
            for (int e = 0; e < 4; e++) acc[mt][nt][e] = 0.f;

    prefetch(0); prefetch(1); prefetch(2);

    for (int s = 0; s < NSTAGE; s++) {
        asm volatile("cp.async.wait_group 2;");
        __syncthreads();
        const int buf = s % 3;
        const uint32_t ab = smb + buf * 49152;
        const uint32_t bb = ab + 16384;
#pragma unroll
        for (int kk = 0; kk < 4; kk++) {
            uint32_t af[4][4];
            const int ar = wm * 64 + (lane & 15);
            const int ac = kk * 2 + (lane >> 4);
#pragma unroll
            for (int mt = 0; mt < 4; mt++) {
                uint32_t o = (ar + mt * 16) * 128 + ac * 16; o ^= (o >> 3) & 0x70;
                ldsm4(af[mt], ab + o);
            }
            uint32_t bfr[8][2];
            const int br = wn * 64 + ((lane >> 4) << 3) + (lane & 7);
            const int bc = kk * 2 + ((lane >> 3) & 1);
#pragma unroll
            for (int np = 0; np < 4; np++) {
                uint32_t o = (br + np * 16) * 128 + bc * 16; o ^= (o >> 3) & 0x70;
                uint32_t t4[4];
                ldsm4(t4, bb + o);
                bfr[np*2][0] = t4[0]; bfr[np*2][1] = t4[1];
                bfr[np*2+1][0] = t4[2]; bfr[np*2+1][1] = t4[3];
            }
#pragma unroll
            for (int mt = 0; mt < 4; mt++)
#pragma unroll
                for (int nt = 0; nt < 8; nt++)
                    mma16816(acc[mt][nt], af[mt], bfr[nt]);
        }
        __syncthreads();
        if (s + 3 < NSTAGE) prefetch(s + 3);
        else asm volatile("cp.async.commit_group;");
    }

    const int er = lane >> 2;
    const int ec = (lane & 3) * 2;
#pragma unroll
    for (int mt = 0; mt < 4; mt++) {
        int r0 = bm + wm * 64 + mt * 16 + er;
#pragma unroll
        for (int nt = 0; nt < 8; nt++) {
            int cc = bn + wn * 64 + nt * 8 + ec;
            *(float2*)(C + (size_t)r0 * N + cc) = make_float2(acc[mt][nt][0], acc[mt][nt][1]);
            *(float2*)(C + (size_t)(r0 + 8) * N + cc) = make_float2(acc[mt][nt][2], acc[mt][nt][3]);
        }
    }
}

// ---------------------------------------------------------------------------
// RoPE in-place on q and k.
// ---------------------------------------------------------------------------
__global__ void rope_kernel(float* __restrict__ q, float* __restrict__ k)
{
    int i = blockIdx.x * blockDim.x + threadIdx.x;
    if (i >= CB*CT*CH*32) return;
    int half = i & 31;
    int rest = i >> 5;
    int t = (rest / CH) & (CT - 1);
    float inv = expf(-(float)half * (1.0f/32.0f) * logf(10000.0f));
    float ang = (float)t * inv;
    float sv, cv;
    sincosf(ang, &sv, &cv);
    size_t base = (size_t)rest * CDH;
    float x0 = q[base + half], x1 = q[base + half + 32];
    q[base + half]      = x0 * cv - x1 * sv;
    q[base + half + 32] = x1 * cv + x0 * sv;
    float y0 = k[base + half], y1 = k[base + half + 32];
    k[base + half]      = y0 * cv - y1 * sv;
    k[base + half + 32] = y1 * cv + y0 * sv;
}

// ---------------------------------------------------------------------------
// conv: q/k/v fp32 -> bf16 h/l pairs (q pre-scaled by 0.125*log2e)
// ---------------------------------------------------------------------------
#define QSCALE 0.180336878f   // 0.125 * log2(e)

__device__ __forceinline__ void split8(const float* src, float scale,
                                       __nv_bfloat16* oh, __nv_bfloat16* ol)
{
    float4 v0 = *(const float4*)src, v1 = *(const float4*)(src + 4);
    float vv[8] = {v0.x,v0.y,v0.z,v0.w,v1.x,v1.y,v1.z,v1.w};
    uint32_t hw[4], lw[4];
#pragma unroll
    for (int e = 0; e < 4; e++) {
        float a = vv[2*e] * scale, b = vv[2*e+1] * scale;
        float ah = __bfloat162float(__float2bfloat16_rn(a));
        float bh = __bfloat162float(__float2bfloat16_rn(b));
        hw[e] = packbf(a, b);
        lw[e] = packbf(a - ah, b - bh);
    }
    *(uint4*)oh = *(uint4*)hw;
    *(uint4*)ol = *(uint4*)lw;
}

__global__ void conv_kernel(const float* __restrict__ q, const float* __restrict__ k,
                            const float* __restrict__ v)
{
    int i = (blockIdx.x * blockDim.x + threadIdx.x) * 8;
    if (i >= MROWS*CDIM) return;
    split8(q + i, QSCALE, g_qh + i, g_ql + i);
    split8(k + i, 1.0f,   g_kh + i, g_kl + i);
    split8(v + i, 1.0f,   g_vh + i, g_vl + i);
}

// ---------------------------------------------------------------------------
// Tensor-core causal flash attention.
// CTA = (b, h, 128 q-rows). 8 warps 2(M)x4(N). j-tiles of 128.
// S = Q'.K'^T with d' = 192 (3-term split). P split (ph+pl) staged in smem.
// PV = ph.vh + ph.vl + pl.vh with ldmatrix.trans V fragments.
// ---------------------------------------------------------------------------
#define AQH 0
#define AQL 16384
#define AKH 32768
#define AKL 49152
#define AVH 65536
#define AVL 81920
#define APH 98304
#define APL 133120
#define ARED 167936
#define ATT_SMEM 172032
#define PROW 272   // P row stride bytes (128 bf16 + pad)

__global__ __launch_bounds__(256, 1)
void attn_tc_kernel(float* __restrict__ outp)
{
    extern __shared__ char sm[];
    const uint32_t smb = smem_u32(sm);
    float* red0 = (float*)(sm + ARED);          // [4][128]
    float* red1 = (float*)(sm + ARED + 2048);   // [4][128]

    const int tid  = threadIdx.x;
    const int lane = tid & 31;
    const int wid  = tid >> 5;
    const int wm = wid & 1, wn = wid >> 1;
    const int qt = gridDim.x - 1 - blockIdx.x;   // big tiles first
    const int h  = blockIdx.y, b = blockIdx.z;
    const int q0 = qt * 128;

    // Q tiles (once)
#pragma unroll
    for (int it = 0; it < 4; it++) {
        int idx = tid + it * 256;
        int r = idx >> 3, ch = idx & 7;
        uint32_t o = r * 128 + ch * 16; o ^= (o >> 3) & 0x70;
        size_t so = ((size_t)(b*CT + q0 + r)) * CDIM + h * CDH + ch * 8;
        CPA16(smb + AQH + o, g_qh + so);
        CPA16(smb + AQL + o, g_ql + so);
    }
    asm volatile("cp.async.commit_group;");

    float m_run[4][2], l_run[4][2];
    float oacc[4][2][4];
#pragma unroll
    for (int mt = 0; mt < 4; mt++)
#pragma unroll
        for (int p = 0; p < 2; p++) {
            m_run[mt][p] = -1e30f; l_run[mt][p] = 0.f;
            oacc[mt][p][0]=oacc[mt][p][1]=oacc[mt][p][2]=oacc[mt][p][3]=0.f;
        }

    const int rbase = (lane >> 2);     // 0..7
    const int cbase = (lane & 3) * 2;

    for (int jt = 0; jt <= qt; jt++) {
        const int j0 = jt * 128;
        __syncthreads();               // prior tile's K/V reads complete
#pragma unroll
        for (int it = 0; it < 4; it++) {
            int idx = tid + it * 256;
            int r = idx >> 3, ch = idx & 7;
            uint32_t o = r * 128 + ch * 16; o ^= (o >> 3) & 0x70;
            size_t so = ((size_t)(b*CT + j0 + r)) * CDIM + h * CDH + ch * 8;
            CPA16(smb + AKH + o, g_kh + so);
            CPA16(smb + AKL + o, g_kl + so);
            CPA16(smb + AVH + o, g_vh + so);
            CPA16(smb + AVL + o, g_vl + so);
        }
        asm volatile("cp.async.commit_group;");
        asm volatile("cp.async.wait_group 0;");
        __syncthreads();

        // ---- S = Q'.K'^T (12 k16 steps over d'=192) ----
        float sacc[4][4][4];
#pragma unroll
        for (int mt = 0; mt < 4; mt++)
#pragma unroll
            for (int nt = 0; nt < 4; nt++)
#pragma unroll
                for (int e = 0; e < 4; e++) sacc[mt][nt][e] = 0.f;

#pragma unroll
        for (int kk = 0; kk < 12; kk++) {
            const uint32_t qb = smb + (kk < 8 ? AQH : AQL);
            const uint32_t kb = smb + (kk < 4 ? AKH : (kk < 8 ? AKL : AKH));
            const int kin = kk & 3;
            uint32_t af[4][4];
            const int ar = wm * 64 + (lane & 15);
            const int ac = kin * 2 + (lane >> 4);
#pragma unroll
            for (int mt = 0; mt < 4; mt++) {
                uint32_t o = (ar + mt * 16) * 128 + ac * 16; o ^= (o >> 3) & 0x70;
                ldsm4(af[mt], qb + o);
            }
            uint32_t bfr[4][2];
            const int br = wn * 32 + ((lane >> 4) << 3) + (lane & 7);
            const int bc = kin * 2 + ((lane >> 3) & 1);
#pragma unroll
            for (int np = 0; np < 2; np++) {
                uint32_t o = (br + np * 16) * 128 + bc * 16; o ^= (o >> 3) & 0x70;
                uint32_t t4[4];
                ldsm4(t4, kb + o);
                bfr[np*2][0] = t4[0]; bfr[np*2][1] = t4[1];
                bfr[np*2+1][0] = t4[2]; bfr[np*2+1][1] = t4[3];
            }
#pragma unroll
            for (int mt = 0; mt < 4; mt++)
#pragma unroll
                for (int nt = 0; nt < 4; nt++)
                    mma16816(sacc[mt][nt], af[mt], bfr[nt]);
        }

        // ---- causal mask on diagonal tile ----
        if (jt == qt) {
#pragma unroll
            for (int mt = 0; mt < 4; mt++)
#pragma unroll
                for (int nt = 0; nt < 4; nt++)
#pragma unroll
                    for (int e = 0; e < 4; e++) {
                        int row = wm*64 + mt*16 + rbase + (e >> 1) * 8;
                        int col = wn*32 + nt*8 + cbase + (e & 1);
                        if (col > row) sacc[mt][nt][e] = -1e30f;
                    }
        }

        // ---- row max (warp partial -> smem -> combine) ----
        float mnew[4][2], alpha[4][2];
#pragma unroll
        for (int mt = 0; mt < 4; mt++)
#pragma unroll
            for (int p = 0; p < 2; p++) {
                float v = fmaxf(fmaxf(sacc[mt][0][2*p], sacc[mt][0][2*p+1]),
                                fmaxf(sacc[mt][1][2*p], sacc[mt][1][2*p+1]));
                v = fmaxf(v, fmaxf(fmaxf(sacc[mt][2][2*p], sacc[mt][2][2*p+1]),
                                   fmaxf(sacc[mt][3][2*p], sacc[mt][3][2*p+1])));
                v = fmaxf(v, __shfl_xor_sync(0xffffffffu, v, 1));
                v = fmaxf(v, __shfl_xor_sync(0xffffffffu, v, 2));
                if ((lane & 3) == 0)
                    red0[wn * 128 + wm*64 + mt*16 + rbase + p*8] = v;
            }
        __syncthreads();
#pragma unroll
        for (int mt = 0; mt < 4; mt++)
#pragma unroll
            for (int p = 0; p < 2; p++) {
                int row = wm*64 + mt*16 + rbase + p*8;
                float v = fmaxf(fmaxf(red0[row], red0[128 + row]),
                                fmaxf(red0[256 + row], red0[384 + row]));
                float mn = fmaxf(m_run[mt][p], v);
                alpha[mt][p] = ex2f(m_run[mt][p] - mn);
                mnew[mt][p] = mn;
                m_run[mt][p] = mn;
            }

        // ---- P = exp2(S - m), split to smem; local row sums; rescale O ----
        float lsum[4][2] = {{0.f,0.f},{0.f,0.f},{0.f,0.f},{0.f,0.f}};
#pragma unroll
        for (int mt = 0; mt < 4; mt++) {
#pragma unroll
            for (int nt = 0; nt < 4; nt++) {
                int col = wn*32 + nt*8 + cbase;
#pragma unroll
                for (int p = 0; p < 2; p++) {
                    int row = wm*64 + mt*16 + rbase + p*8;
                    float p0 = ex2f(sacc[mt][nt][2*p]   - mnew[mt][p]);
                    float p1 = ex2f(sacc[mt][nt][2*p+1] - mnew[mt][p]);
                    lsum[mt][p] += p0 + p1;
                    float p0h = __bfloat162float(__float2bfloat16_rn(p0));
                    float p1h = __bfloat162float(__float2bfloat16_rn(p1));
                    *(uint32_t*)(sm + APH + row*PROW + col*2) = packbf(p0, p1);
                    *(uint32_t*)(sm + APL + row*PROW + col*2) = packbf(p0 - p0h, p1 - p1h);
                }
            }
        }
#pragma unroll
        for (int mt = 0; mt < 4; mt++)
#pragma unroll
            for (int p = 0; p < 2; p++) {
                float v = lsum[mt][p];
                v += __shfl_xor_sync(0xffffffffu, v, 1);
                v += __shfl_xor_sync(0xffffffffu, v, 2);
                if ((lane & 3) == 0)
                    red1[wn * 128 + wm*64 + mt*16 + rbase + p*8] = v;
                // rescale O by alpha
                oacc[mt][0][2*p]   *= alpha[mt][p];
                oacc[mt][0][2*p+1] *= alpha[mt][p];
                oacc[mt][1][2*p]   *= alpha[mt][p];
                oacc[mt][1][2*p+1] *= alpha[mt][p];
            }
        __syncthreads();     // P + red1 visible
#pragma unroll
        for (int mt = 0; mt < 4; mt++)
#pragma unroll
            for (int p = 0; p < 2; p++) {
                int row = wm*64 + mt*16 + rbase + p*8;
                float v = red1[row] + red1[128 + row] + red1[256 + row] + red1[384 + row];
                l_run[mt][p] = l_run[mt][p] * alpha[mt][p] + v;
            }

        // ---- PV: parts (ph,vh), (ph,vl), (pl,vh) ----
#pragma unroll
        for (int part = 0; part < 3; part++) {
            const uint32_t pb = smb + (part < 2 ? APH : APL);
            const uint32_t vb = smb + (part == 1 ? AVL : AVH);
#pragma unroll
            for (int kk = 0; kk < 8; kk++) {
                uint32_t af[4][4];
                const int ar = wm * 64 + (lane & 15);
                const int ac = kk * 2 + (lane >> 4);
#pragma unroll
                for (int mt = 0; mt < 4; mt++)
                    ldsm4(af[mt], pb + (ar + mt*16)*PROW + ac*16);
                uint32_t bv[2][2];
                const int vr = kk * 16 + (lane & 15);
#pragma unroll
                for (int np = 0; np < 2; np++) {
                    uint32_t o = vr * 128 + (wn*16 + np*8) * 2; o ^= (o >> 3) & 0x70;
                    ldsm2t(bv[np], vb + o);
                }
#pragma unroll
                for (int mt = 0; mt < 4; mt++)
#pragma unroll
                    for (int np = 0; np < 2; np++)
                        mma16816(oacc[mt][np], af[mt], bv[np]);
            }
        }
    }

    // ---- write O / l ----
#pragma unroll
    for (int mt = 0; mt < 4; mt++)
#pragma unroll
        for (int p = 0; p < 2; p++) {
            float inv = 1.0f / l_run[mt][p];
            int row = q0 + wm*64 + mt*16 + rbase + p*8;
#pragma unroll
            for (int np = 0; np < 2; np++) {
                int col = h * CDH + wn*16 + np*8 + cbase;
                *(float2*)(outp + ((size_t)(b*CT) + row) * CDIM + col) =
                    make_float2(oacc[mt][np][2*p] * inv, oacc[mt][np][2*p+1] * inv);
            }
        }
}

// ---------------------------------------------------------------------------
extern "C" void kernel_launch(void* const* d_in, const int* in_sizes, int n_in,
                              void* d_out, int out_size)
{
    const float* x  = (const float*)d_in[0];
    const float* Wq = (const float*)d_in[1];
    const float* Wk = (const float*)d_in[2];
    const float* Wv = (const float*)d_in[3];
    const float* Wo = (const float*)d_in[4];
    float* out = (float*)d_out;

    float *qp, *kp, *vp, *ap;
    __nv_bfloat16 *a2, *wq2, *wk2, *wv2, *wo2;
    cudaGetSymbolAddress((void**)&qp, g_q);
    cudaGetSymbolAddress((void**)&kp, g_k);
    cudaGetSymbolAddress((void**)&vp, g_v);
    cudaGetSymbolAddress((void**)&ap, g_att);
    cudaGetSymbolAddress((void**)&a2, g_a);
    cudaGetSymbolAddress((void**)&wq2, g_wq);
    cudaGetSymbolAddress((void**)&wk2, g_wk);
    cudaGetSymbolAddress((void**)&wv2, g_wv);
    cudaGetSymbolAddress((void**)&wo2, g_wo);

    cudaFuncSetAttribute(gemm_mma_kernel,
                         cudaFuncAttributeMaxDynamicSharedMemorySize, GEMM_SMEM);
    cudaFuncSetAttribute(attn_tc_kernel,
                         cudaFuncAttributeMaxDynamicSharedMemorySize, ATT_SMEM);

    int na = MROWS * 256, nw = CDIM * 256;
    split_kernel<<<(na + 255)/256, 256>>>(x,  a2,  MROWS, 0);
    split_kernel<<<(nw + 255)/256, 256>>>(Wq, wq2, CDIM, 1);
    split_kernel<<<(nw + 255)/256, 256>>>(Wk, wk2, CDIM, 1);
    split_kernel<<<(nw + 255)/256, 256>>>(Wv, wv2, CDIM, 1);
    split_kernel<<<(nw + 255)/256, 256>>>(Wo, wo2, CDIM, 1);

    dim3 gg(CDIM/256, MROWS/128);   // (4, 32)
    gemm_mma_kernel<<<gg, 256, GEMM_SMEM>>>(a2, wq2, qp, MROWS, CDIM);
    gemm_mma_kernel<<<gg, 256, GEMM_SMEM>>>(a2, wk2, kp, MROWS, CDIM);
    gemm_mma_kernel<<<gg, 256, GEMM_SMEM>>>(a2, wv2, vp, MROWS, CDIM);

    int nrope = CB*CT*CH*32;
    rope_kernel<<<(nrope + 255)/256, 256>>>(qp, kp);

    conv_kernel<<<(MROWS*CDIM/8 + 255)/256, 256>>>(qp, kp, vp);

    attn_tc_kernel<<<dim3(CT/128, CH, CB), 256, ATT_SMEM>>>(ap);

    split_kernel<<<(na + 255)/256, 256>>>(ap, a2, MROWS, 0);
    gemm_mma_kernel<<<gg, 256, GEMM_SMEM>>>(a2, wo2, out, MROWS, CDIM);
}

// round 8
// speedup vs baseline: 3.3545x; 1.1940x over previous
#include <cuda_runtime.h>
#include <cuda_bf16.h>
#include <cuda_fp16.h>
#include <math.h>
#include <cstdint>

#define CB   2
#define CT   2048
#define CDIM 1024
#define CH   16
#define CDH  64
#define MROWS (CB*CT)       // 4096
#define KSPLIT (3*CDIM)     // 3072
#define NSTAGE (KSPLIT/64)  // 48

// ---------------- scratch (device globals) ----------------------------------
__device__ float g_q[MROWS*CDIM];
__device__ float g_k[MROWS*CDIM];
__device__ float g_v[MROWS*CDIM];
__device__ __nv_bfloat16 g_a [MROWS*KSPLIT];   // split activations [Ah|Ah|Al]
__device__ __nv_bfloat16 g_wq[CDIM*KSPLIT];    // split weights     [Bh|Bl|Bh]
__device__ __nv_bfloat16 g_wk[CDIM*KSPLIT];
__device__ __nv_bfloat16 g_wv[CDIM*KSPLIT];
__device__ __nv_bfloat16 g_wo[CDIM*KSPLIT];
// pre-split attention operands
__device__ __nv_bfloat16 g_qh[MROWS*CDIM];
__device__ __nv_bfloat16 g_ql[MROWS*CDIM];
__device__ __nv_bfloat16 g_kh[MROWS*CDIM];
__device__ __nv_bfloat16 g_kl[MROWS*CDIM];
__device__ __half        g_vh[MROWS*CDIM];     // fp16 V

__device__ __forceinline__ uint32_t smem_u32(const void* p) {
    uint32_t a;
    asm("{ .reg .u64 t; cvta.to.shared.u64 t, %1; cvt.u32.u64 %0, t; }"
        : "=r"(a) : "l"(p));
    return a;
}
__device__ __forceinline__ void ldsm4(uint32_t* r, uint32_t addr) {
    asm volatile("ldmatrix.sync.aligned.m8n8.x4.shared.b16 {%0,%1,%2,%3}, [%4];"
        : "=r"(r[0]), "=r"(r[1]), "=r"(r[2]), "=r"(r[3]) : "r"(addr));
}
__device__ __forceinline__ void ldsm2t(uint32_t* r, uint32_t addr) {
    asm volatile("ldmatrix.sync.aligned.m8n8.x2.trans.shared.b16 {%0,%1}, [%2];"
        : "=r"(r[0]), "=r"(r[1]) : "r"(addr));
}
__device__ __forceinline__ void mma16816(float* d, const uint32_t* a, const uint32_t* b) {
    asm volatile("mma.sync.aligned.m16n8k16.row.col.f32.bf16.bf16.f32 "
        "{%0,%1,%2,%3}, {%4,%5,%6,%7}, {%8,%9}, {%0,%1,%2,%3};"
        : "+f"(d[0]), "+f"(d[1]), "+f"(d[2]), "+f"(d[3])
        : "r"(a[0]), "r"(a[1]), "r"(a[2]), "r"(a[3]), "r"(b[0]), "r"(b[1]));
}
__device__ __forceinline__ void mma16816h(float* d, const uint32_t* a, const uint32_t* b) {
    asm volatile("mma.sync.aligned.m16n8k16.row.col.f32.f16.f16.f32 "
        "{%0,%1,%2,%3}, {%4,%5,%6,%7}, {%8,%9}, {%0,%1,%2,%3};"
        : "+f"(d[0]), "+f"(d[1]), "+f"(d[2]), "+f"(d[3])
        : "r"(a[0]), "r"(a[1]), "r"(a[2]), "r"(a[3]), "r"(b[0]), "r"(b[1]));
}
__device__ __forceinline__ float ex2f(float x) {
    float y; asm("ex2.approx.f32 %0, %1;" : "=f"(y) : "f"(x)); return y;
}
__device__ __forceinline__ uint32_t packbf(float a, float b) {
    __nv_bfloat162 t = __floats2bfloat162_rn(a, b);
    return *(uint32_t*)&t;
}
__device__ __forceinline__ uint32_t packhf(float a, float b) {
    __half2 t = __floats2half2_rn(a, b);
    return *(uint32_t*)&t;
}
#define CPA16(dst, src) \
    asm volatile("cp.async.cg.shared.global [%0], [%1], 16;" :: "r"(dst), "l"(src))

// ---------------------------------------------------------------------------
// split activations: fp32 [rows x 1024] -> bf16 [rows x 3072] [h|h|l]
// ---------------------------------------------------------------------------
__global__ void split_kernel(const float* __restrict__ in,
                             __nv_bfloat16* __restrict__ out, int rows)
{
    int i = blockIdx.x * blockDim.x + threadIdx.x;
    if (i >= rows * 256) return;
    int r  = i >> 8;
    int c4 = (i & 255) * 4;
    float4 v = *(const float4*)(in + (size_t)r * CDIM + c4);
    __nv_bfloat16 h[4], l[4];
    float vs[4] = {v.x, v.y, v.z, v.w};
#pragma unroll
    for (int t = 0; t < 4; t++) {
        h[t] = __float2bfloat16(vs[t]);
        l[t] = __float2bfloat16(vs[t] - __bfloat162float(h[t]));
    }
    __nv_bfloat16* o = out + (size_t)r * KSPLIT + c4;
    *(ushort4*)(o)            = *(ushort4*)h;
    *(ushort4*)(o + CDIM)     = *(ushort4*)h;
    *(ushort4*)(o + 2 * CDIM) = *(ushort4*)l;
}

// 4 weight splits in one launch: [h|l|h]
__global__ void splitw_kernel(const float* __restrict__ Wq, const float* __restrict__ Wk,
                              const float* __restrict__ Wv, const float* __restrict__ Wo)
{
    int z = blockIdx.y;
    const float* in = (z == 0) ? Wq : (z == 1) ? Wk : (z == 2) ? Wv : Wo;
    __nv_bfloat16* out = (z == 0) ? g_wq : (z == 1) ? g_wk : (z == 2) ? g_wv : g_wo;
    int i = blockIdx.x * blockDim.x + threadIdx.x;
    if (i >= CDIM * 256) return;
    int r  = i >> 8;
    int c4 = (i & 255) * 4;
    float4 v = *(const float4*)(in + (size_t)r * CDIM + c4);
    __nv_bfloat16 h[4], l[4];
    float vs[4] = {v.x, v.y, v.z, v.w};
#pragma unroll
    for (int t = 0; t < 4; t++) {
        h[t] = __float2bfloat16(vs[t]);
        l[t] = __float2bfloat16(vs[t] - __bfloat162float(h[t]));
    }
    __nv_bfloat16* o = out + (size_t)r * KSPLIT + c4;
    *(ushort4*)(o)            = *(ushort4*)h;
    *(ushort4*)(o + CDIM)     = *(ushort4*)l;
    *(ushort4*)(o + 2 * CDIM) = *(ushort4*)h;
}

// ---------------------------------------------------------------------------
// mma.sync bf16 NT GEMM: C = A'[M,3072] * B'[N,3072]^T, fp32 accum.
// CTA 128x256, 8 warps 2x4 (64x64 warp tiles), 3-stage cp.async.
// ---------------------------------------------------------------------------
#define GEMM_SMEM (3*49152)

__global__ __launch_bounds__(256, 1)
void gemm_mma_kernel(const __nv_bfloat16* __restrict__ A,
                     const __nv_bfloat16* __restrict__ B,
                     float* __restrict__ C, int M, int N)
{
    extern __shared__ char sm[];
    const uint32_t smb = smem_u32(sm);
    const int tid  = threadIdx.x;
    const int lane = tid & 31;
    const int wid  = tid >> 5;
    const int wm = wid & 1;
    const int wn = wid >> 1;
    const int bm = blockIdx.y * 128;
    const int bn = blockIdx.x * 256;

    const __nv_bfloat16* Ag = A + (size_t)bm * KSPLIT;
    const __nv_bfloat16* Bg = B + (size_t)bn * KSPLIT;

    auto prefetch = [&](int s) {
        const int buf = s % 3;
        const uint32_t ab = smb + buf * 49152;
        const uint32_t bb = ab + 16384;
        const __nv_bfloat16* a = Ag + s * 64;
        const __nv_bfloat16* b = Bg + s * 64;
#pragma unroll
        for (int i = 0; i < 4; i++) {
            int idx = tid + i * 256;
            int r = idx >> 3, ch = idx & 7;
            uint32_t o = r * 128 + ch * 16; o ^= (o >> 3) & 0x70;
            CPA16(ab + o, a + (size_t)r * KSPLIT + ch * 8);
        }
#pragma unroll
        for (int i = 0; i < 8; i++) {
            int idx = tid + i * 256;
            int r = idx >> 3, ch = idx & 7;
            uint32_t o = r * 128 + ch * 16; o ^= (o >> 3) & 0x70;
            CPA16(bb + o, b + (size_t)r * KSPLIT + ch * 8);
        }
        asm volatile("cp.async.commit_group;");
    };

    float acc[4][8][4];
#pragma unroll
    for (int mt = 0; mt < 4; mt++)
#pragma unroll
        for (int nt = 0; nt < 8; nt++)
#pragma unroll
            for (int e = 0; e < 4; e++) acc[mt][nt][e] = 0.f;

    prefetch(0); prefetch(1); prefetch(2);

    for (int s = 0; s < NSTAGE; s++) {
        asm volatile("cp.async.wait_group 2;");
        __syncthreads();
        const int buf = s % 3;
        const uint32_t ab = smb + buf * 49152;
        const uint32_t bb = ab + 16384;
#pragma unroll
        for (int kk = 0; kk < 4; kk++) {
            uint32_t af[4][4];
            const int ar = wm * 64 + (lane & 15);
            const int ac = kk * 2 + (lane >> 4);
#pragma unroll
            for (int mt = 0; mt < 4; mt++) {
                uint32_t o = (ar + mt * 16) * 128 + ac * 16; o ^= (o >> 3) & 0x70;
                ldsm4(af[mt], ab + o);
            }
            uint32_t bfr[8][2];
            const int br = wn * 64 + ((lane >> 4) << 3) + (lane & 7);
            const int bc = kk * 2 + ((lane >> 3) & 1);
#pragma unroll
            for (int np = 0; np < 4; np++) {
                uint32_t o = (br + np * 16) * 128 + bc * 16; o ^= (o >> 3) & 0x70;
                uint32_t t4[4];
                ldsm4(t4, bb + o);
                bfr[np*2][0] = t4[0]; bfr[np*2][1] = t4[1];
                bfr[np*2+1][0] = t4[2]; bfr[np*2+1][1] = t4[3];
            }
#pragma unroll
            for (int mt = 0; mt < 4; mt++)
#pragma unroll
                for (int nt = 0; nt < 8; nt++)
                    mma16816(acc[mt][nt], af[mt], bfr[nt]);
        }
        __syncthreads();
        if (s + 3 < NSTAGE) prefetch(s + 3);
        else asm volatile("cp.async.commit_group;");
    }

    const int er = lane >> 2;
    const int ec = (lane & 3) * 2;
#pragma unroll
    for (int mt = 0; mt < 4; mt++) {
        int r0 = bm + wm * 64 + mt * 16 + er;
#pragma unroll
        for (int nt = 0; nt < 8; nt++) {
            int cc = bn + wn * 64 + nt * 8 + ec;
            *(float2*)(C + (size_t)r0 * N + cc) = make_float2(acc[mt][nt][0], acc[mt][nt][1]);
            *(float2*)(C + (size_t)(r0 + 8) * N + cc) = make_float2(acc[mt][nt][2], acc[mt][nt][3]);
        }
    }
}

// ---------------------------------------------------------------------------
// fused RoPE + split conversion. q pre-scaled by 0.125*log2e. V -> fp16.
// ---------------------------------------------------------------------------
#define QSCALE 0.180336878f   // 0.125 * log2(e)

__global__ void ropeconv_kernel(const float* __restrict__ q,
                                const float* __restrict__ k,
                                const float* __restrict__ v)
{
    int i = blockIdx.x * blockDim.x + threadIdx.x;
    if (i >= MROWS * CH * 4) return;
    const int c8   = (i & 3) * 8;
    const int rest = i >> 2;                 // (b*CT+t)*CH + h
    const int t    = (rest >> 4) & (CT - 1);
    const size_t base = (size_t)rest * CDH;

    float q0[8], q1[8], k0[8], k1[8], v0[8], v1[8];
    *(float4*)(q0)   = *(const float4*)(q + base + c8);
    *(float4*)(q0+4) = *(const float4*)(q + base + c8 + 4);
    *(float4*)(q1)   = *(const float4*)(q + base + c8 + 32);
    *(float4*)(q1+4) = *(const float4*)(q + base + c8 + 36);
    *(float4*)(k0)   = *(const float4*)(k + base + c8);
    *(float4*)(k0+4) = *(const float4*)(k + base + c8 + 4);
    *(float4*)(k1)   = *(const float4*)(k + base + c8 + 32);
    *(float4*)(k1+4) = *(const float4*)(k + base + c8 + 36);
    *(float4*)(v0)   = *(const float4*)(v + base + c8);
    *(float4*)(v0+4) = *(const float4*)(v + base + c8 + 4);
    *(float4*)(v1)   = *(const float4*)(v + base + c8 + 32);
    *(float4*)(v1+4) = *(const float4*)(v + base + c8 + 36);

#pragma unroll
    for (int d = 0; d < 8; d++) {
        float invf = expf(-(float)(c8 + d) * (1.0f/32.0f) * logf(10000.0f));
        float ang = (float)t * invf, sv, cv;
        sincosf(ang, &sv, &cv);
        float a = q0[d], bq = q1[d];
        q0[d] = a * cv - bq * sv;  q1[d] = bq * cv + a * sv;
        float c = k0[d], dk = k1[d];
        k0[d] = c * cv - dk * sv;  k1[d] = dk * cv + c * sv;
    }

    uint32_t hw[4], lw[4];
    auto emit = [&](const float* src, float scale,
                    __nv_bfloat16* oh, __nv_bfloat16* ol) {
#pragma unroll
        for (int e = 0; e < 4; e++) {
            float a = src[2*e] * scale, b = src[2*e+1] * scale;
            float ah = __bfloat162float(__float2bfloat16_rn(a));
            float bh = __bfloat162float(__float2bfloat16_rn(b));
            hw[e] = packbf(a, b);
            lw[e] = packbf(a - ah, b - bh);
        }
        *(uint4*)oh = *(uint4*)hw;
        *(uint4*)ol = *(uint4*)lw;
    };
    auto emith = [&](const float* src, __half* oh) {
#pragma unroll
        for (int e = 0; e < 4; e++)
            hw[e] = packhf(src[2*e], src[2*e+1]);
        *(uint4*)oh = *(uint4*)hw;
    };
    emit(q0, QSCALE, g_qh + base + c8,      g_ql + base + c8);
    emit(q1, QSCALE, g_qh + base + c8 + 32, g_ql + base + c8 + 32);
    emit(k0, 1.0f,   g_kh + base + c8,      g_kl + base + c8);
    emit(k1, 1.0f,   g_kh + base + c8 + 32, g_kl + base + c8 + 32);
    emith(v0, g_vh + base + c8);
    emith(v1, g_vh + base + c8 + 32);
}

// ---------------------------------------------------------------------------
// Tensor-core causal flash attention.
// CTA = (b, h, 128 q-rows). 8 warps 2(M)x4(N). j-tiles of 128.
// S: 3-term bf16 split (d'=192). PV: single term, fp16 P x fp16 V.
// K/V double-buffered. Epilogue writes split [h|h|l] bf16 into g_a.
// ---------------------------------------------------------------------------
#define AQH 0
#define AQL 16384
#define AKV 32768          // + buf*49152 : KH +0, KL +16384, VH(fp16) +32768
#define APH 131072
#define ARED 165888
#define ATT_SMEM 169984
#define PROW 272           // P row stride bytes

__global__ __launch_bounds__(256, 1)
void attn_tc_kernel()
{
    extern __shared__ char sm[];
    const uint32_t smb = smem_u32(sm);
    float* red0 = (float*)(sm + ARED);
    float* red1 = (float*)(sm + ARED + 2048);

    const int tid  = threadIdx.x;
    const int lane = tid & 31;
    const int wid  = tid >> 5;
    const int wm = wid & 1, wn = wid >> 1;
    const int qt = gridDim.x - 1 - blockIdx.x;
    const int h  = blockIdx.y, b = blockIdx.z;
    const int q0 = qt * 128;

    // Q tiles
#pragma unroll
    for (int it = 0; it < 4; it++) {
        int idx = tid + it * 256;
        int r = idx >> 3, ch = idx & 7;
        uint32_t o = r * 128 + ch * 16; o ^= (o >> 3) & 0x70;
        size_t so = ((size_t)(b*CT + q0 + r)) * CDIM + h * CDH + ch * 8;
        CPA16(smb + AQH + o, g_qh + so);
        CPA16(smb + AQL + o, g_ql + so);
    }
    asm volatile("cp.async.commit_group;");

    auto pf_kv = [&](int jtn) {
        const uint32_t kvb = smb + AKV + (jtn & 1) * 49152;
        const int j0n = jtn * 128;
#pragma unroll
        for (int it = 0; it < 4; it++) {
            int idx = tid + it * 256;
            int r = idx >> 3, ch = idx & 7;
            uint32_t o = r * 128 + ch * 16; o ^= (o >> 3) & 0x70;
            size_t so = ((size_t)(b*CT + j0n + r)) * CDIM + h * CDH + ch * 8;
            CPA16(kvb + o,         g_kh + so);
            CPA16(kvb + 16384 + o, g_kl + so);
            CPA16(kvb + 32768 + o, g_vh + so);
        }
    };
    pf_kv(0);
    asm volatile("cp.async.commit_group;");

    float m_run[4][2], l_run[4][2];
    float oacc[4][2][4];
#pragma unroll
    for (int mt = 0; mt < 4; mt++)
#pragma unroll
        for (int p = 0; p < 2; p++) {
            m_run[mt][p] = -1e30f; l_run[mt][p] = 0.f;
            oacc[mt][p][0]=oacc[mt][p][1]=oacc[mt][p][2]=oacc[mt][p][3]=0.f;
        }

    const int rbase = (lane >> 2);
    const int cbase = (lane & 3) * 2;

    for (int jt = 0; jt <= qt; jt++) {
        __syncthreads();
        if (jt < qt) pf_kv(jt + 1);
        asm volatile("cp.async.commit_group;");
        asm volatile("cp.async.wait_group 1;");
        __syncthreads();

        const uint32_t kvb = smb + AKV + (jt & 1) * 49152;

        // ---- S = Q'.K'^T (12 k16 steps over d'=192) ----
        float sacc[4][4][4];
#pragma unroll
        for (int mt = 0; mt < 4; mt++)
#pragma unroll
            for (int nt = 0; nt < 4; nt++)
#pragma unroll
                for (int e = 0; e < 4; e++) sacc[mt][nt][e] = 0.f;

#pragma unroll
        for (int kk = 0; kk < 12; kk++) {
            const uint32_t qb = smb + (kk < 8 ? AQH : AQL);
            const uint32_t kb = kvb + (kk < 4 ? 0 : (kk < 8 ? 16384 : 0));
            const int kin = kk & 3;
            uint32_t af[4][4];
            const int ar = wm * 64 + (lane & 15);
            const int ac = kin * 2 + (lane >> 4);
#pragma unroll
            for (int mt = 0; mt < 4; mt++) {
                uint32_t o = (ar + mt * 16) * 128 + ac * 16; o ^= (o >> 3) & 0x70;
                ldsm4(af[mt], qb + o);
            }
            uint32_t bfr[4][2];
            const int br = wn * 32 + ((lane >> 4) << 3) + (lane & 7);
            const int bc = kin * 2 + ((lane >> 3) & 1);
#pragma unroll
            for (int np = 0; np < 2; np++) {
                uint32_t o = (br + np * 16) * 128 + bc * 16; o ^= (o >> 3) & 0x70;
                uint32_t t4[4];
                ldsm4(t4, kb + o);
                bfr[np*2][0] = t4[0]; bfr[np*2][1] = t4[1];
                bfr[np*2+1][0] = t4[2]; bfr[np*2+1][1] = t4[3];
            }
#pragma unroll
            for (int mt = 0; mt < 4; mt++)
#pragma unroll
                for (int nt = 0; nt < 4; nt++)
                    mma16816(sacc[mt][nt], af[mt], bfr[nt]);
        }

        if (jt == qt) {
#pragma unroll
            for (int mt = 0; mt < 4; mt++)
#pragma unroll
                for (int nt = 0; nt < 4; nt++)
#pragma unroll
                    for (int e = 0; e < 4; e++) {
                        int row = wm*64 + mt*16 + rbase + (e >> 1) * 8;
                        int col = wn*32 + nt*8 + cbase + (e & 1);
                        if (col > row) sacc[mt][nt][e] = -1e30f;
                    }
        }

        // ---- row max ----
        float mnew[4][2], alpha[4][2];
#pragma unroll
        for (int mt = 0; mt < 4; mt++)
#pragma unroll
            for (int p = 0; p < 2; p++) {
                float v = fmaxf(fmaxf(sacc[mt][0][2*p], sacc[mt][0][2*p+1]),
                                fmaxf(sacc[mt][1][2*p], sacc[mt][1][2*p+1]));
                v = fmaxf(v, fmaxf(fmaxf(sacc[mt][2][2*p], sacc[mt][2][2*p+1]),
                                   fmaxf(sacc[mt][3][2*p], sacc[mt][3][2*p+1])));
                v = fmaxf(v, __shfl_xor_sync(0xffffffffu, v, 1));
                v = fmaxf(v, __shfl_xor_sync(0xffffffffu, v, 2));
                if ((lane & 3) == 0)
                    red0[wn * 128 + wm*64 + mt*16 + rbase + p*8] = v;
            }
        __syncthreads();
#pragma unroll
        for (int mt = 0; mt < 4; mt++)
#pragma unroll
            for (int p = 0; p < 2; p++) {
                int row = wm*64 + mt*16 + rbase + p*8;
                float v = fmaxf(fmaxf(red0[row], red0[128 + row]),
                                fmaxf(red0[256 + row], red0[384 + row]));
                float mn = fmaxf(m_run[mt][p], v);
                alpha[mt][p] = ex2f(m_run[mt][p] - mn);
                mnew[mt][p] = mn;
                m_run[mt][p] = mn;
            }

        // ---- P = exp2(S - m) -> fp16 smem; row sums; rescale O ----
        float lsum[4][2] = {{0.f,0.f},{0.f,0.f},{0.f,0.f},{0.f,0.f}};
#pragma unroll
        for (int mt = 0; mt < 4; mt++) {
#pragma unroll
            for (int nt = 0; nt < 4; nt++) {
                int col = wn*32 + nt*8 + cbase;
#pragma unroll
                for (int p = 0; p < 2; p++) {
                    int row = wm*64 + mt*16 + rbase + p*8;
                    float p0 = ex2f(sacc[mt][nt][2*p]   - mnew[mt][p]);
                    float p1 = ex2f(sacc[mt][nt][2*p+1] - mnew[mt][p]);
                    lsum[mt][p] += p0 + p1;
                    *(uint32_t*)(sm + APH + row*PROW + col*2) = packhf(p0, p1);
                }
            }
        }
#pragma unroll
        for (int mt = 0; mt < 4; mt++)
#pragma unroll
            for (int p = 0; p < 2; p++) {
                float v = lsum[mt][p];
                v += __shfl_xor_sync(0xffffffffu, v, 1);
                v += __shfl_xor_sync(0xffffffffu, v, 2);
                if ((lane & 3) == 0)
                    red1[wn * 128 + wm*64 + mt*16 + rbase + p*8] = v;
                oacc[mt][0][2*p]   *= alpha[mt][p];
                oacc[mt][0][2*p+1] *= alpha[mt][p];
                oacc[mt][1][2*p]   *= alpha[mt][p];
                oacc[mt][1][2*p+1] *= alpha[mt][p];
            }
        __syncthreads();
#pragma unroll
        for (int mt = 0; mt < 4; mt++)
#pragma unroll
            for (int p = 0; p < 2; p++) {
                int row = wm*64 + mt*16 + rbase + p*8;
                float v = red1[row] + red1[128 + row] + red1[256 + row] + red1[384 + row];
                l_run[mt][p] = l_run[mt][p] * alpha[mt][p] + v;
            }

        // ---- PV: single term, fp16 P x fp16 V ----
        const uint32_t vb = kvb + 32768;
#pragma unroll
        for (int kk = 0; kk < 8; kk++) {
            uint32_t af[4][4];
            const int ar = wm * 64 + (lane & 15);
            const int ac = kk * 2 + (lane >> 4);
#pragma unroll
            for (int mt = 0; mt < 4; mt++)
                ldsm4(af[mt], smb + APH + (ar + mt*16)*PROW + ac*16);
            uint32_t bv[2][2];
            const int vr = kk * 16 + (lane & 15);
#pragma unroll
            for (int np = 0; np < 2; np++) {
                uint32_t o = vr * 128 + (wn*16 + np*8) * 2; o ^= (o >> 3) & 0x70;
                ldsm2t(bv[np], vb + o);
            }
#pragma unroll
            for (int mt = 0; mt < 4; mt++)
#pragma unroll
                for (int np = 0; np < 2; np++)
                    mma16816h(oacc[mt][np], af[mt], bv[np]);
        }
    }

    // ---- epilogue: write split activations [h|h|l] straight into g_a ----
#pragma unroll
    for (int mt = 0; mt < 4; mt++)
#pragma unroll
        for (int p = 0; p < 2; p++) {
            float inv = 1.0f / l_run[mt][p];
            size_t rg = (size_t)(b*CT) + q0 + wm*64 + mt*16 + rbase + p*8;
#pragma unroll
            for (int np = 0; np < 2; np++) {
                int col = h * CDH + wn*16 + np*8 + cbase;
                float v0 = oacc[mt][np][2*p] * inv;
                float v1 = oacc[mt][np][2*p+1] * inv;
                float h0 = __bfloat162float(__float2bfloat16_rn(v0));
                float h1 = __bfloat162float(__float2bfloat16_rn(v1));
                uint32_t hwv = packbf(v0, v1);
                uint32_t lwv = packbf(v0 - h0, v1 - h1);
                __nv_bfloat16* oa = g_a + rg * KSPLIT + col;
                *(uint32_t*)(oa)            = hwv;
                *(uint32_t*)(oa + CDIM)     = hwv;
                *(uint32_t*)(oa + 2*CDIM)   = lwv;
            }
        }
}

// ---------------------------------------------------------------------------
extern "C" void kernel_launch(void* const* d_in, const int* in_sizes, int n_in,
                              void* d_out, int out_size)
{
    const float* x  = (const float*)d_in[0];
    const float* Wq = (const float*)d_in[1];
    const float* Wk = (const float*)d_in[2];
    const float* Wv = (const float*)d_in[3];
    const float* Wo = (const float*)d_in[4];
    float* out = (float*)d_out;

    float *qp, *kp, *vp;
    __nv_bfloat16 *a2, *wq2, *wk2, *wv2, *wo2;
    cudaGetSymbolAddress((void**)&qp, g_q);
    cudaGetSymbolAddress((void**)&kp, g_k);
    cudaGetSymbolAddress((void**)&vp, g_v);
    cudaGetSymbolAddress((void**)&a2, g_a);
    cudaGetSymbolAddress((void**)&wq2, g_wq);
    cudaGetSymbolAddress((void**)&wk2, g_wk);
    cudaGetSymbolAddress((void**)&wv2, g_wv);
    cudaGetSymbolAddress((void**)&wo2, g_wo);

    cudaFuncSetAttribute(gemm_mma_kernel,
                         cudaFuncAttributeMaxDynamicSharedMemorySize, GEMM_SMEM);
    cudaFuncSetAttribute(attn_tc_kernel,
                         cudaFuncAttributeMaxDynamicSharedMemorySize, ATT_SMEM);

    int na = MROWS * 256;
    split_kernel<<<(na + 255)/256, 256>>>(x, a2, MROWS);
    splitw_kernel<<<dim3(CDIM, 4), 256>>>(Wq, Wk, Wv, Wo);

    dim3 gg(CDIM/256, MROWS/128);   // (4, 32)
    gemm_mma_kernel<<<gg, 256, GEMM_SMEM>>>(a2, wq2, qp, MROWS, CDIM);
    gemm_mma_kernel<<<gg, 256, GEMM_SMEM>>>(a2, wk2, kp, MROWS, CDIM);
    gemm_mma_kernel<<<gg, 256, GEMM_SMEM>>>(a2, wv2, vp, MROWS, CDIM);

    ropeconv_kernel<<<(MROWS*CH*4 + 255)/256, 256>>>(qp, kp, vp);

    attn_tc_kernel<<<dim3(CT/128, CH, CB), 256, ATT_SMEM>>>();

    gemm_mma_kernel<<<gg, 256, GEMM_SMEM>>>(a2, wo2, out, MROWS, CDIM);
}

// round 11
// speedup vs baseline: 3.4111x; 1.0169x over previous
#include <cuda_runtime.h>
#include <cuda_bf16.h>
#include <cuda_fp16.h>
#include <math.h>
#include <cstdint>

#define CB   2
#define CT   2048
#define CDIM 1024
#define CH   16
#define CDH  64
#define MROWS (CB*CT)       // 4096
#define KSPLIT (3*CDIM)     // 3072
#define NSTAGE (KSPLIT/64)  // 48

// ---------------- scratch (device globals) ----------------------------------
__device__ float g_q[MROWS*CDIM];
__device__ float g_k[MROWS*CDIM];
__device__ float g_v[MROWS*CDIM];
__device__ __nv_bfloat16 g_a [MROWS*KSPLIT];   // split activations [Ah|Ah|Al]
__device__ __nv_bfloat16 g_wq[CDIM*KSPLIT];    // split weights     [Bh|Bl|Bh]
__device__ __nv_bfloat16 g_wk[CDIM*KSPLIT];
__device__ __nv_bfloat16 g_wv[CDIM*KSPLIT];
__device__ __nv_bfloat16 g_wo[CDIM*KSPLIT];
// pre-split attention operands
__device__ __nv_bfloat16 g_qh[MROWS*CDIM];
__device__ __nv_bfloat16 g_ql[MROWS*CDIM];
__device__ __nv_bfloat16 g_kh[MROWS*CDIM];
__device__ __nv_bfloat16 g_kl[MROWS*CDIM];
__device__ __half        g_vh[MROWS*CDIM];     // fp16 V

__device__ __forceinline__ uint32_t smem_u32(const void* p) {
    uint32_t a;
    asm("{ .reg .u64 t; cvta.to.shared.u64 t, %1; cvt.u32.u64 %0, t; }"
        : "=r"(a) : "l"(p));
    return a;
}
__device__ __forceinline__ void ldsm4(uint32_t* r, uint32_t addr) {
    asm volatile("ldmatrix.sync.aligned.m8n8.x4.shared.b16 {%0,%1,%2,%3}, [%4];"
        : "=r"(r[0]), "=r"(r[1]), "=r"(r[2]), "=r"(r[3]) : "r"(addr));
}
__device__ __forceinline__ void ldsm2t(uint32_t* r, uint32_t addr) {
    asm volatile("ldmatrix.sync.aligned.m8n8.x2.trans.shared.b16 {%0,%1}, [%2];"
        : "=r"(r[0]), "=r"(r[1]) : "r"(addr));
}
__device__ __forceinline__ void mma16816(float* d, const uint32_t* a, const uint32_t* b) {
    asm volatile("mma.sync.aligned.m16n8k16.row.col.f32.bf16.bf16.f32 "
        "{%0,%1,%2,%3}, {%4,%5,%6,%7}, {%8,%9}, {%0,%1,%2,%3};"
        : "+f"(d[0]), "+f"(d[1]), "+f"(d[2]), "+f"(d[3])
        : "r"(a[0]), "r"(a[1]), "r"(a[2]), "r"(a[3]), "r"(b[0]), "r"(b[1]));
}
__device__ __forceinline__ void mma16816h(float* d, const uint32_t* a, const uint32_t* b) {
    asm volatile("mma.sync.aligned.m16n8k16.row.col.f32.f16.f16.f32 "
        "{%0,%1,%2,%3}, {%4,%5,%6,%7}, {%8,%9}, {%0,%1,%2,%3};"
        : "+f"(d[0]), "+f"(d[1]), "+f"(d[2]), "+f"(d[3])
        : "r"(a[0]), "r"(a[1]), "r"(a[2]), "r"(a[3]), "r"(b[0]), "r"(b[1]));
}
__device__ __forceinline__ float ex2f(float x) {
    float y; asm("ex2.approx.f32 %0, %1;" : "=f"(y) : "f"(x)); return y;
}
__device__ __forceinline__ uint32_t packbf(float a, float b) {
    __nv_bfloat162 t = __floats2bfloat162_rn(a, b);
    return *(uint32_t*)&t;
}
__device__ __forceinline__ uint32_t packhf(float a, float b) {
    __half2 t = __floats2half2_rn(a, b);
    return *(uint32_t*)&t;
}
#define CPA16(dst, src) \
    asm volatile("cp.async.cg.shared.global [%0], [%1], 16;" :: "r"(dst), "l"(src))

// ---------------------------------------------------------------------------
// split activations: fp32 [rows x 1024] -> bf16 [rows x 3072] [h|h|l]
// ---------------------------------------------------------------------------
__global__ void split_kernel(const float* __restrict__ in,
                             __nv_bfloat16* __restrict__ out, int rows)
{
    int i = blockIdx.x * blockDim.x + threadIdx.x;
    if (i >= rows * 256) return;
    int r  = i >> 8;
    int c4 = (i & 255) * 4;
    float4 v = *(const float4*)(in + (size_t)r * CDIM + c4);
    __nv_bfloat16 h[4], l[4];
    float vs[4] = {v.x, v.y, v.z, v.w};
#pragma unroll
    for (int t = 0; t < 4; t++) {
        h[t] = __float2bfloat16(vs[t]);
        l[t] = __float2bfloat16(vs[t] - __bfloat162float(h[t]));
    }
    __nv_bfloat16* o = out + (size_t)r * KSPLIT + c4;
    *(ushort4*)(o)            = *(ushort4*)h;
    *(ushort4*)(o + CDIM)     = *(ushort4*)h;
    *(ushort4*)(o + 2 * CDIM) = *(ushort4*)l;
}

// 4 weight splits in one launch: [h|l|h]
__global__ void splitw_kernel(const float* __restrict__ Wq, const float* __restrict__ Wk,
                              const float* __restrict__ Wv, const float* __restrict__ Wo)
{
    int z = blockIdx.y;
    const float* in = (z == 0) ? Wq : (z == 1) ? Wk : (z == 2) ? Wv : Wo;
    __nv_bfloat16* out = (z == 0) ? g_wq : (z == 1) ? g_wk : (z == 2) ? g_wv : g_wo;
    int i = blockIdx.x * blockDim.x + threadIdx.x;
    if (i >= CDIM * 256) return;
    int r  = i >> 8;
    int c4 = (i & 255) * 4;
    float4 v = *(const float4*)(in + (size_t)r * CDIM + c4);
    __nv_bfloat16 h[4], l[4];
    float vs[4] = {v.x, v.y, v.z, v.w};
#pragma unroll
    for (int t = 0; t < 4; t++) {
        h[t] = __float2bfloat16(vs[t]);
        l[t] = __float2bfloat16(vs[t] - __bfloat162float(h[t]));
    }
    __nv_bfloat16* o = out + (size_t)r * KSPLIT + c4;
    *(ushort4*)(o)            = *(ushort4*)h;
    *(ushort4*)(o + CDIM)     = *(ushort4*)l;
    *(ushort4*)(o + 2 * CDIM) = *(ushort4*)h;
}

// ---------------------------------------------------------------------------
// mma.sync bf16 NT GEMM: C = A'[M,3072] * B'[N,3072]^T, fp32 accum.
// CTA 128x128, 8 warps 2(m)x4(n) with 64x32 warp tiles, 3-stage cp.async,
// 96KB smem -> 2 CTAs/SM (16 warps) for latency hiding.
// ---------------------------------------------------------------------------
#define GEMM_SMEM (3*32768)

__global__ __launch_bounds__(256, 2)
void gemm_mma_kernel(const __nv_bfloat16* __restrict__ A,
                     const __nv_bfloat16* __restrict__ B,
                     float* __restrict__ C, int M, int N)
{
    extern __shared__ char sm[];
    const uint32_t smb = smem_u32(sm);
    const int tid  = threadIdx.x;
    const int lane = tid & 31;
    const int wid  = tid >> 5;
    const int wm = wid & 1;    // 0..1 -> 64 rows
    const int wn = wid >> 1;   // 0..3 -> 32 cols
    const int bm = blockIdx.y * 128;
    const int bn = blockIdx.x * 128;

    const __nv_bfloat16* Ag = A + (size_t)bm * KSPLIT;
    const __nv_bfloat16* Bg = B + (size_t)bn * KSPLIT;

    auto prefetch = [&](int s) {
        const int buf = s % 3;
        const uint32_t ab = smb + buf * 32768;
        const uint32_t bb = ab + 16384;
        const __nv_bfloat16* a = Ag + s * 64;
        const __nv_bfloat16* b = Bg + s * 64;
#pragma unroll
        for (int i = 0; i < 4; i++) {
            int idx = tid + i * 256;
            int r = idx >> 3, ch = idx & 7;
            uint32_t o = r * 128 + ch * 16; o ^= (o >> 3) & 0x70;
            CPA16(ab + o, a + (size_t)r * KSPLIT + ch * 8);
            CPA16(bb + o, b + (size_t)r * KSPLIT + ch * 8);
        }
        asm volatile("cp.async.commit_group;");
    };

    float acc[4][4][4];
#pragma unroll
    for (int mt = 0; mt < 4; mt++)
#pragma unroll
        for (int nt = 0; nt < 4; nt++)
#pragma unroll
            for (int e = 0; e < 4; e++) acc[mt][nt][e] = 0.f;

    prefetch(0); prefetch(1); prefetch(2);

    for (int s = 0; s < NSTAGE; s++) {
        asm volatile("cp.async.wait_group 2;");
        __syncthreads();
        const int buf = s % 3;
        const uint32_t ab = smb + buf * 32768;
        const uint32_t bb = ab + 16384;
#pragma unroll
        for (int kk = 0; kk < 4; kk++) {
            uint32_t af[4][4];
            const int ar = wm * 64 + (lane & 15);
            const int ac = kk * 2 + (lane >> 4);
#pragma unroll
            for (int mt = 0; mt < 4; mt++) {
                uint32_t o = (ar + mt * 16) * 128 + ac * 16; o ^= (o >> 3) & 0x70;
                ldsm4(af[mt], ab + o);
            }
            uint32_t bfr[4][2];
            const int br = wn * 32 + ((lane >> 4) << 3) + (lane & 7);
            const int bc = kk * 2 + ((lane >> 3) & 1);
#pragma unroll
            for (int np = 0; np < 2; np++) {
                uint32_t o = (br + np * 16) * 128 + bc * 16; o ^= (o >> 3) & 0x70;
                uint32_t t4[4];
                ldsm4(t4, bb + o);
                bfr[np*2][0] = t4[0]; bfr[np*2][1] = t4[1];
                bfr[np*2+1][0] = t4[2]; bfr[np*2+1][1] = t4[3];
            }
#pragma unroll
            for (int mt = 0; mt < 4; mt++)
#pragma unroll
                for (int nt = 0; nt < 4; nt++)
                    mma16816(acc[mt][nt], af[mt], bfr[nt]);
        }
        __syncthreads();
        if (s + 3 < NSTAGE) prefetch(s + 3);
        else asm volatile("cp.async.commit_group;");
    }

    const int er = lane >> 2;
    const int ec = (lane & 3) * 2;
#pragma unroll
    for (int mt = 0; mt < 4; mt++) {
        int r0 = bm + wm * 64 + mt * 16 + er;
#pragma unroll
        for (int nt = 0; nt < 4; nt++) {
            int cc = bn + wn * 32 + nt * 8 + ec;
            *(float2*)(C + (size_t)r0 * N + cc) = make_float2(acc[mt][nt][0], acc[mt][nt][1]);
            *(float2*)(C + (size_t)(r0 + 8) * N + cc) = make_float2(acc[mt][nt][2], acc[mt][nt][3]);
        }
    }
}

// ---------------------------------------------------------------------------
// fused RoPE + split conversion. q pre-scaled by 0.125*log2e. V -> fp16.
// ---------------------------------------------------------------------------
#define QSCALE 0.180336878f   // 0.125 * log2(e)

__global__ void ropeconv_kernel(const float* __restrict__ q,
                                const float* __restrict__ k,
                                const float* __restrict__ v)
{
    int i = blockIdx.x * blockDim.x + threadIdx.x;
    if (i >= MROWS * CH * 4) return;
    const int c8   = (i & 3) * 8;
    const int rest = i >> 2;                 // (b*CT+t)*CH + h
    const int t    = (rest >> 4) & (CT - 1);
    const size_t base = (size_t)rest * CDH;

    float q0[8], q1[8], k0[8], k1[8], v0[8], v1[8];
    *(float4*)(q0)   = *(const float4*)(q + base + c8);
    *(float4*)(q0+4) = *(const float4*)(q + base + c8 + 4);
    *(float4*)(q1)   = *(const float4*)(q + base + c8 + 32);
    *(float4*)(q1+4) = *(const float4*)(q + base + c8 + 36);
    *(float4*)(k0)   = *(const float4*)(k + base + c8);
    *(float4*)(k0+4) = *(const float4*)(k + base + c8 + 4);
    *(float4*)(k1)   = *(const float4*)(k + base + c8 + 32);
    *(float4*)(k1+4) = *(const float4*)(k + base + c8 + 36);
    *(float4*)(v0)   = *(const float4*)(v + base + c8);
    *(float4*)(v0+4) = *(const float4*)(v + base + c8 + 4);
    *(float4*)(v1)   = *(const float4*)(v + base + c8 + 32);
    *(float4*)(v1+4) = *(const float4*)(v + base + c8 + 36);

#pragma unroll
    for (int d = 0; d < 8; d++) {
        float invf = expf(-(float)(c8 + d) * (1.0f/32.0f) * logf(10000.0f));
        float ang = (float)t * invf, sv, cv;
        sincosf(ang, &sv, &cv);
        float a = q0[d], bq = q1[d];
        q0[d] = a * cv - bq * sv;  q1[d] = bq * cv + a * sv;
        float c = k0[d], dk = k1[d];
        k0[d] = c * cv - dk * sv;  k1[d] = dk * cv + c * sv;
    }

    uint32_t hw[4], lw[4];
    auto emit = [&](const float* src, float scale,
                    __nv_bfloat16* oh, __nv_bfloat16* ol) {
#pragma unroll
        for (int e = 0; e < 4; e++) {
            float a = src[2*e] * scale, b = src[2*e+1] * scale;
            float ah = __bfloat162float(__float2bfloat16_rn(a));
            float bh = __bfloat162float(__float2bfloat16_rn(b));
            hw[e] = packbf(a, b);
            lw[e] = packbf(a - ah, b - bh);
        }
        *(uint4*)oh = *(uint4*)hw;
        *(uint4*)ol = *(uint4*)lw;
    };
    auto emith = [&](const float* src, __half* oh) {
#pragma unroll
        for (int e = 0; e < 4; e++)
            hw[e] = packhf(src[2*e], src[2*e+1]);
        *(uint4*)oh = *(uint4*)hw;
    };
    emit(q0, QSCALE, g_qh + base + c8,      g_ql + base + c8);
    emit(q1, QSCALE, g_qh + base + c8 + 32, g_ql + base + c8 + 32);
    emit(k0, 1.0f,   g_kh + base + c8,      g_kl + base + c8);
    emit(k1, 1.0f,   g_kh + base + c8 + 32, g_kl + base + c8 + 32);
    emith(v0, g_vh + base + c8);
    emith(v1, g_vh + base + c8 + 32);
}

// ---------------------------------------------------------------------------
// Tensor-core causal flash attention.
// CTA = (b, h, 128 q-rows). 8 warps 2(M)x4(N). j-tiles of 128.
// S: 3-term bf16 split (d'=192). PV: single term, fp16 P x fp16 V.
// K/V double-buffered. Epilogue writes split [h|h|l] bf16 into g_a.
// ---------------------------------------------------------------------------
#define AQH 0
#define AQL 16384
#define AKV 32768          // + buf*49152 : KH +0, KL +16384, VH(fp16) +32768
#define APH 131072
#define ARED 165888
#define ATT_SMEM 169984
#define PROW 272           // P row stride bytes

__global__ __launch_bounds__(256, 1)
void attn_tc_kernel()
{
    extern __shared__ char sm[];
    const uint32_t smb = smem_u32(sm);
    float* red0 = (float*)(sm + ARED);
    float* red1 = (float*)(sm + ARED + 2048);

    const int tid  = threadIdx.x;
    const int lane = tid & 31;
    const int wid  = tid >> 5;
    const int wm = wid & 1, wn = wid >> 1;
    const int qt = gridDim.x - 1 - blockIdx.x;
    const int h  = blockIdx.y, b = blockIdx.z;
    const int q0 = qt * 128;

    // Q tiles
#pragma unroll
    for (int it = 0; it < 4; it++) {
        int idx = tid + it * 256;
        int r = idx >> 3, ch = idx & 7;
        uint32_t o = r * 128 + ch * 16; o ^= (o >> 3) & 0x70;
        size_t so = ((size_t)(b*CT + q0 + r)) * CDIM + h * CDH + ch * 8;
        CPA16(smb + AQH + o, g_qh + so);
        CPA16(smb + AQL + o, g_ql + so);
    }
    asm volatile("cp.async.commit_group;");

    auto pf_kv = [&](int jtn) {
        const uint32_t kvb = smb + AKV + (jtn & 1) * 49152;
        const int j0n = jtn * 128;
#pragma unroll
        for (int it = 0; it < 4; it++) {
            int idx = tid + it * 256;
            int r = idx >> 3, ch = idx & 7;
            uint32_t o = r * 128 + ch * 16; o ^= (o >> 3) & 0x70;
            size_t so = ((size_t)(b*CT + j0n + r)) * CDIM + h * CDH + ch * 8;
            CPA16(kvb + o,         g_kh + so);
            CPA16(kvb + 16384 + o, g_kl + so);
            CPA16(kvb + 32768 + o, g_vh + so);
        }
    };
    pf_kv(0);
    asm volatile("cp.async.commit_group;");

    float m_run[4][2], l_run[4][2];
    float oacc[4][2][4];
#pragma unroll
    for (int mt = 0; mt < 4; mt++)
#pragma unroll
        for (int p = 0; p < 2; p++) {
            m_run[mt][p] = -1e30f; l_run[mt][p] = 0.f;
            oacc[mt][p][0]=oacc[mt][p][1]=oacc[mt][p][2]=oacc[mt][p][3]=0.f;
        }

    const int rbase = (lane >> 2);
    const int cbase = (lane & 3) * 2;

    for (int jt = 0; jt <= qt; jt++) {
        __syncthreads();
        if (jt < qt) pf_kv(jt + 1);
        asm volatile("cp.async.commit_group;");
        asm volatile("cp.async.wait_group 1;");
        __syncthreads();

        const uint32_t kvb = smb + AKV + (jt & 1) * 49152;

        // ---- S = Q'.K'^T (12 k16 steps over d'=192) ----
        float sacc[4][4][4];
#pragma unroll
        for (int mt = 0; mt < 4; mt++)
#pragma unroll
            for (int nt = 0; nt < 4; nt++)
#pragma unroll
                for (int e = 0; e < 4; e++) sacc[mt][nt][e] = 0.f;

#pragma unroll
        for (int kk = 0; kk < 12; kk++) {
            const uint32_t qb = smb + (kk < 8 ? AQH : AQL);
            const uint32_t kb = kvb + (kk < 4 ? 0 : (kk < 8 ? 16384 : 0));
            const int kin = kk & 3;
            uint32_t af[4][4];
            const int ar = wm * 64 + (lane & 15);
            const int ac = kin * 2 + (lane >> 4);
#pragma unroll
            for (int mt = 0; mt < 4; mt++) {
                uint32_t o = (ar + mt * 16) * 128 + ac * 16; o ^= (o >> 3) & 0x70;
                ldsm4(af[mt], qb + o);
            }
            uint32_t bfr[4][2];
            const int br = wn * 32 + ((lane >> 4) << 3) + (lane & 7);
            const int bc = kin * 2 + ((lane >> 3) & 1);
#pragma unroll
            for (int np = 0; np < 2; np++) {
                uint32_t o = (br + np * 16) * 128 + bc * 16; o ^= (o >> 3) & 0x70;
                uint32_t t4[4];
                ldsm4(t4, kb + o);
                bfr[np*2][0] = t4[0]; bfr[np*2][1] = t4[1];
                bfr[np*2+1][0] = t4[2]; bfr[np*2+1][1] = t4[3];
            }
#pragma unroll
            for (int mt = 0; mt < 4; mt++)
#pragma unroll
                for (int nt = 0; nt < 4; nt++)
                    mma16816(sacc[mt][nt], af[mt], bfr[nt]);
        }

        if (jt == qt) {
#pragma unroll
            for (int mt = 0; mt < 4; mt++)
#pragma unroll
                for (int nt = 0; nt < 4; nt++)
#pragma unroll
                    for (int e = 0; e < 4; e++) {
                        int row = wm*64 + mt*16 + rbase + (e >> 1) * 8;
                        int col = wn*32 + nt*8 + cbase + (e & 1);
                        if (col > row) sacc[mt][nt][e] = -1e30f;
                    }
        }

        // ---- row max ----
        float mnew[4][2], alpha[4][2];
#pragma unroll
        for (int mt = 0; mt < 4; mt++)
#pragma unroll
            for (int p = 0; p < 2; p++) {
                float v = fmaxf(fmaxf(sacc[mt][0][2*p], sacc[mt][0][2*p+1]),
                                fmaxf(sacc[mt][1][2*p], sacc[mt][1][2*p+1]));
                v = fmaxf(v, fmaxf(fmaxf(sacc[mt][2][2*p], sacc[mt][2][2*p+1]),
                                   fmaxf(sacc[mt][3][2*p], sacc[mt][3][2*p+1])));
                v = fmaxf(v, __shfl_xor_sync(0xffffffffu, v, 1));
                v = fmaxf(v, __shfl_xor_sync(0xffffffffu, v, 2));
                if ((lane & 3) == 0)
                    red0[wn * 128 + wm*64 + mt*16 + rbase + p*8] = v;
            }
        __syncthreads();
#pragma unroll
        for (int mt = 0; mt < 4; mt++)
#pragma unroll
            for (int p = 0; p < 2; p++) {
                int row = wm*64 + mt*16 + rbase + p*8;
                float v = fmaxf(fmaxf(red0[row], red0[128 + row]),
                                fmaxf(red0[256 + row], red0[384 + row]));
                float mn = fmaxf(m_run[mt][p], v);
                alpha[mt][p] = ex2f(m_run[mt][p] - mn);
                mnew[mt][p] = mn;
                m_run[mt][p] = mn;
            }

        // ---- P = exp2(S - m) -> fp16 smem; row sums; rescale O ----
        float lsum[4][2] = {{0.f,0.f},{0.f,0.f},{0.f,0.f},{0.f,0.f}};
#pragma unroll
        for (int mt = 0; mt < 4; mt++) {
#pragma unroll
            for (int nt = 0; nt < 4; nt++) {
                int col = wn*32 + nt*8 + cbase;
#pragma unroll
                for (int p = 0; p < 2; p++) {
                    int row = wm*64 + mt*16 + rbase + p*8;
                    float p0 = ex2f(sacc[mt][nt][2*p]   - mnew[mt][p]);
                    float p1 = ex2f(sacc[mt][nt][2*p+1] - mnew[mt][p]);
                    lsum[mt][p] += p0 + p1;
                    *(uint32_t*)(sm + APH + row*PROW + col*2) = packhf(p0, p1);
                }
            }
        }
#pragma unroll
        for (int mt = 0; mt < 4; mt++)
#pragma unroll
            for (int p = 0; p < 2; p++) {
                float v = lsum[mt][p];
                v += __shfl_xor_sync(0xffffffffu, v, 1);
                v += __shfl_xor_sync(0xffffffffu, v, 2);
                if ((lane & 3) == 0)
                    red1[wn * 128 + wm*64 + mt*16 + rbase + p*8] = v;
                oacc[mt][0][2*p]   *= alpha[mt][p];
                oacc[mt][0][2*p+1] *= alpha[mt][p];
                oacc[mt][1][2*p]   *= alpha[mt][p];
                oacc[mt][1][2*p+1] *= alpha[mt][p];
            }
        __syncthreads();
#pragma unroll
        for (int mt = 0; mt < 4; mt++)
#pragma unroll
            for (int p = 0; p < 2; p++) {
                int row = wm*64 + mt*16 + rbase + p*8;
                float v = red1[row] + red1[128 + row] + red1[256 + row] + red1[384 + row];
                l_run[mt][p] = l_run[mt][p] * alpha[mt][p] + v;
            }

        // ---- PV: single term, fp16 P x fp16 V ----
        const uint32_t vb = kvb + 32768;
#pragma unroll
        for (int kk = 0; kk < 8; kk++) {
            uint32_t af[4][4];
            const int ar = wm * 64 + (lane & 15);
            const int ac = kk * 2 + (lane >> 4);
#pragma unroll
            for (int mt = 0; mt < 4; mt++)
                ldsm4(af[mt], smb + APH + (ar + mt*16)*PROW + ac*16);
            uint32_t bv[2][2];
            const int vr = kk * 16 + (lane & 15);
#pragma unroll
            for (int np = 0; np < 2; np++) {
                uint32_t o = vr * 128 + (wn*16 + np*8) * 2; o ^= (o >> 3) & 0x70;
                ldsm2t(bv[np], vb + o);
            }
#pragma unroll
            for (int mt = 0; mt < 4; mt++)
#pragma unroll
                for (int np = 0; np < 2; np++)
                    mma16816h(oacc[mt][np], af[mt], bv[np]);
        }
    }

    // ---- epilogue: write split activations [h|h|l] straight into g_a ----
#pragma unroll
    for (int mt = 0; mt < 4; mt++)
#pragma unroll
        for (int p = 0; p < 2; p++) {
            float inv = 1.0f / l_run[mt][p];
            size_t rg = (size_t)(b*CT) + q0 + wm*64 + mt*16 + rbase + p*8;
#pragma unroll
            for (int np = 0; np < 2; np++) {
                int col = h * CDH + wn*16 + np*8 + cbase;
                float v0 = oacc[mt][np][2*p] * inv;
                float v1 = oacc[mt][np][2*p+1] * inv;
                float h0 = __bfloat162float(__float2bfloat16_rn(v0));
                float h1 = __bfloat162float(__float2bfloat16_rn(v1));
                uint32_t hwv = packbf(v0, v1);
                uint32_t lwv = packbf(v0 - h0, v1 - h1);
                __nv_bfloat16* oa = g_a + rg * KSPLIT + col;
                *(uint32_t*)(oa)            = hwv;
                *(uint32_t*)(oa + CDIM)     = hwv;
                *(uint32_t*)(oa + 2*CDIM)   = lwv;
            }
        }
}

// ---------------------------------------------------------------------------
extern "C" void kernel_launch(void* const* d_in, const int* in_sizes, int n_in,
                              void* d_out, int out_size)
{
    const float* x  = (const float*)d_in[0];
    const float* Wq = (const float*)d_in[1];
    const float* Wk = (const float*)d_in[2];
    const float* Wv = (const float*)d_in[3];
    const float* Wo = (const float*)d_in[4];
    float* out = (float*)d_out;

    float *qp, *kp, *vp;
    __nv_bfloat16 *a2, *wq2, *wk2, *wv2, *wo2;
    cudaGetSymbolAddress((void**)&qp, g_q);
    cudaGetSymbolAddress((void**)&kp, g_k);
    cudaGetSymbolAddress((void**)&vp, g_v);
    cudaGetSymbolAddress((void**)&a2, g_a);
    cudaGetSymbolAddress((void**)&wq2, g_wq);
    cudaGetSymbolAddress((void**)&wk2, g_wk);
    cudaGetSymbolAddress((void**)&wv2, g_wv);
    cudaGetSymbolAddress((void**)&wo2, g_wo);

    cudaFuncSetAttribute(gemm_mma_kernel,
                         cudaFuncAttributeMaxDynamicSharedMemorySize, GEMM_SMEM);
    cudaFuncSetAttribute(attn_tc_kernel,
                         cudaFuncAttributeMaxDynamicSharedMemorySize, ATT_SMEM);

    int na = MROWS * 256;
    split_kernel<<<(na + 255)/256, 256>>>(x, a2, MROWS);
    splitw_kernel<<<dim3(CDIM, 4), 256>>>(Wq, Wk, Wv, Wo);

    dim3 gg(CDIM/128, MROWS/128);   // (8, 32) = 256 CTAs
    gemm_mma_kernel<<<gg, 256, GEMM_SMEM>>>(a2, wq2, qp, MROWS, CDIM);
    gemm_mma_kernel<<<gg, 256, GEMM_SMEM>>>(a2, wk2, kp, MROWS, CDIM);
    gemm_mma_kernel<<<gg, 256, GEMM_SMEM>>>(a2, wv2, vp, MROWS, CDIM);

    ropeconv_kernel<<<(MROWS*CH*4 + 255)/256, 256>>>(qp, kp, vp);

    attn_tc_kernel<<<dim3(CT/128, CH, CB), 256, ATT_SMEM>>>();

    gemm_mma_kernel<<<gg, 256, GEMM_SMEM>>>(a2, wo2, out, MROWS, CDIM);
}